// round 5
// baseline (speedup 1.0000x reference)
#include <cuda_runtime.h>
#include <cuda_bf16.h>
#include <cstdint>
#include <cstddef>

// ---------------------------------------------------------------------------
// ASTGCN block, fp32.  Shapes: B=16, N=1024, F=32, T=24, K=3, CC=CT=64.
// ---------------------------------------------------------------------------

constexpr int NB  = 16;
constexpr int NN  = 1024;
constexpr int NF  = 32;
constexpr int NT  = 24;
constexpr int NK  = 3;
constexpr int NCC = 64;
constexpr int NCT = 64;
constexpr int FT  = NF * NT;   // 768

// ------------------------- scratch (device globals) ------------------------
__device__ float g_lhs_t[NB * NT * NF];
__device__ float g_rhs_t[NB * NN * NT];
__device__ float g_Epre[NB * NT * NT];
__device__ float g_E[NB * NT * NT];
__device__ float g_xTAt[(size_t)NB * NN * FT];
__device__ float g_lhs2s[NB * NN * NT];
__device__ float g_rhs_s[NB * NT * NN];
__device__ float g_Spre[(size_t)NB * NN * NN];
__device__ float g_cmax[NB * NN];
__device__ float g_Sexp[(size_t)NB * NN * NN];
__device__ float g_csum[NB * NN];
__device__ float g_rhs_all[(size_t)NK * NB * NN * FT];

// ------------------------------ helpers ------------------------------------
__device__ __forceinline__ void ffma2(unsigned long long& d,
                                      unsigned long long a,
                                      unsigned long long b) {
    asm("fma.rn.f32x2 %0, %1, %2, %0;" : "+l"(d) : "l"(a), "l"(b));
}
__device__ __forceinline__ unsigned long long pack2(float x) {
    unsigned long long r;
    asm("mov.b64 %0, {%1, %1};" : "=l"(r) : "f"(x));
    return r;
}
__device__ __forceinline__ float lo32(unsigned long long v) {
    return __uint_as_float((unsigned)(v & 0xffffffffull));
}
__device__ __forceinline__ float hi32(unsigned long long v) {
    return __uint_as_float((unsigned)(v >> 32));
}

// ---------------------------------------------------------------------------
// K1: lhs_t[b,t,f] = sum_n x[b,n,f,t] * U1[n]           grid(NT,NB) x 256
// ---------------------------------------------------------------------------
__global__ void __launch_bounds__(256) k_lhs_t(const float* __restrict__ x,
                                               const float* __restrict__ U1) {
    int t = blockIdx.x, b = blockIdx.y;
    int w = threadIdx.x >> 5, lane = threadIdx.x & 31;
    const float* xb = x + (size_t)b * NN * FT;
    for (int f = w; f < NF; f += 8) {
        float s = 0.f;
        for (int n = lane; n < NN; n += 32)
            s += xb[(size_t)n * FT + f * NT + t] * U1[n];
        #pragma unroll
        for (int o = 16; o; o >>= 1) s += __shfl_xor_sync(0xffffffffu, s, o);
        if (lane == 0) g_lhs_t[(b * NT + t) * NF + f] = s;
    }
}

// ---------------------------------------------------------------------------
// K2: rhs_t[b,n,t] = sum_f U3[f] * x[b,n,f,t]           grid(NN/32,NB) x 256
// ---------------------------------------------------------------------------
__global__ void __launch_bounds__(256) k_rhs_t(const float* __restrict__ x,
                                               const float* __restrict__ U3) {
    int b = blockIdx.y, n0 = blockIdx.x * 32;
    int tid = threadIdx.x;
    const float* xb = x + (size_t)b * NN * FT;
    int e0 = tid, e1 = tid + 256, e2 = tid + 512;  // over 32n x 24t = 768
    size_t b0 = (size_t)(n0 + e0 / 24) * FT + (e0 % 24);
    size_t b1 = (size_t)(n0 + e1 / 24) * FT + (e1 % 24);
    size_t b2 = (size_t)(n0 + e2 / 24) * FT + (e2 % 24);
    float a0 = 0.f, a1 = 0.f, a2 = 0.f;
    #pragma unroll
    for (int f = 0; f < NF; f++) {
        float u = U3[f];
        int off = f * NT;
        a0 += u * xb[b0 + off];
        a1 += u * xb[b1 + off];
        a2 += u * xb[b2 + off];
    }
    float* o = g_rhs_t + (size_t)b * NN * NT + (size_t)n0 * NT;
    o[e0] = a0; o[e1] = a1; o[e2] = a2;
}

// ---------------------------------------------------------------------------
// K3: E_pre[b,t,s] = sum_n (sum_f lhs_t[b,t,f]U2[f,n]) * rhs_t[b,n,s]
//                                                        grid(NT,NB) x 256
// ---------------------------------------------------------------------------
__global__ void __launch_bounds__(256) k_epre(const float* __restrict__ U2) {
    int t = blockIdx.x, b = blockIdx.y;
    __shared__ float lt[NF];
    __shared__ float red[8][NT];
    int tid = threadIdx.x;
    if (tid < NF) lt[tid] = g_lhs_t[(b * NT + t) * NF + tid];
    __syncthreads();
    float pe[NT];
    #pragma unroll
    for (int s = 0; s < NT; s++) pe[s] = 0.f;
    for (int n = tid; n < NN; n += 256) {
        float l2 = 0.f;
        #pragma unroll
        for (int f = 0; f < NF; f++) l2 += lt[f] * U2[f * NN + n];
        const float* rr = &g_rhs_t[((size_t)b * NN + n) * NT];
        #pragma unroll
        for (int s = 0; s < NT; s++) pe[s] += l2 * rr[s];
    }
    int lane = tid & 31, w = tid >> 5;
    #pragma unroll
    for (int s = 0; s < NT; s++) {
        float v = pe[s];
        #pragma unroll
        for (int o = 16; o; o >>= 1) v += __shfl_xor_sync(0xffffffffu, v, o);
        if (lane == 0) red[w][s] = v;
    }
    __syncthreads();
    if (tid < NT) {
        float v = 0.f;
        #pragma unroll
        for (int w2 = 0; w2 < 8; w2++) v += red[w2][tid];
        g_Epre[b * NT * NT + t * NT + tid] = v;
    }
}

// ---------------------------------------------------------------------------
// K4: E = softmax(E_pre, axis=t)   one warp per (b,s)    grid(NT,NB) x 32
// ---------------------------------------------------------------------------
__global__ void k_esm() {
    int s = blockIdx.x, b = blockIdx.y, lane = threadIdx.x;
    float v = (lane < NT) ? g_Epre[b * NT * NT + lane * NT + s] : -3.4e38f;
    float mx = v;
    #pragma unroll
    for (int o = 16; o; o >>= 1) mx = fmaxf(mx, __shfl_xor_sync(0xffffffffu, mx, o));
    float e = (lane < NT) ? __expf(v - mx) : 0.f;
    float sm = e;
    #pragma unroll
    for (int o = 16; o; o >>= 1) sm += __shfl_xor_sync(0xffffffffu, sm, o);
    if (lane < NT) g_E[b * NT * NT + lane * NT + s] = e / sm;
}

// ---------------------------------------------------------------------------
// K5: x_TAt[b,n,f,s] = sum_t x[b,n,f,t]*E[b,t,s]        grid(NB*128) x 256
// ---------------------------------------------------------------------------
__global__ void __launch_bounds__(256) k_xtat(const float* __restrict__ x) {
    int b = blockIdx.x >> 7;  // 128 blocks per b
    size_t row = (size_t)blockIdx.x * 256 + threadIdx.x;  // (b,n,f) row
    __shared__ float Es[NT * NT];
    for (int i = threadIdx.x; i < NT * NT; i += 256) Es[i] = g_E[b * NT * NT + i];
    __syncthreads();
    float in[NT];
    const float4* ip = (const float4*)(x + row * NT);
    #pragma unroll
    for (int i = 0; i < 6; i++) ((float4*)in)[i] = ip[i];
    float o[NT];
    #pragma unroll
    for (int s = 0; s < NT; s++) {
        float a = 0.f;
        #pragma unroll
        for (int t = 0; t < NT; t++) a += in[t] * Es[t * NT + s];
        o[s] = a;
    }
    float4* op = (float4*)(g_xTAt + row * NT);
    #pragma unroll
    for (int i = 0; i < 6; i++) op[i] = ((float4*)o)[i];
}

// ---------------------------------------------------------------------------
// K6: lhs2s[b,n,t] = sum_f (sum_t' xTAt[b,n,f,t']W1[t']) * W2[f,t]
//                                                        grid(NB*128) x 256
// ---------------------------------------------------------------------------
__global__ void __launch_bounds__(256) k_lhs2s(const float* __restrict__ W1,
                                               const float* __restrict__ W2) {
    int bb = blockIdx.x;
    int b = bb >> 7;
    int n0 = (bb & 127) * 8;
    __shared__ float ls[8][NF];
    int tid = threadIdx.x;
    int ni = tid >> 5, f = tid & 31;
    const float* r = g_xTAt + ((size_t)(b * NN + n0 + ni) * NF + f) * NT;
    float s = 0.f;
    #pragma unroll
    for (int t = 0; t < NT; t++) s += r[t] * W1[t];
    ls[ni][f] = s;
    __syncthreads();
    if (tid < 8 * NT) {
        int ni2 = tid / NT, t = tid - ni2 * NT;
        float v = 0.f;
        #pragma unroll
        for (int ff = 0; ff < NF; ff++) v += ls[ni2][ff] * W2[ff * NT + t];
        g_lhs2s[((size_t)b * NN + n0 + ni2) * NT + t] = v;
    }
}

// ---------------------------------------------------------------------------
// K7: rhs_s[b,t,m] = sum_f W3[f] * xTAt[b,m,f,t]        grid(NN/32,NB) x 256
// ---------------------------------------------------------------------------
__global__ void __launch_bounds__(256) k_rhs_s(const float* __restrict__ W3) {
    int b = blockIdx.y, m0 = blockIdx.x * 32;
    int tid = threadIdx.x;
    const float* xb = g_xTAt + (size_t)b * NN * FT;
    int e0 = tid, e1 = tid + 256, e2 = tid + 512;  // 32m x 24t
    int m_0 = e0 / 24, t_0 = e0 - m_0 * 24;
    int m_1 = e1 / 24, t_1 = e1 - m_1 * 24;
    int m_2 = e2 / 24, t_2 = e2 - m_2 * 24;
    size_t b0 = (size_t)(m0 + m_0) * FT + t_0;
    size_t b1 = (size_t)(m0 + m_1) * FT + t_1;
    size_t b2 = (size_t)(m0 + m_2) * FT + t_2;
    float a0 = 0.f, a1 = 0.f, a2 = 0.f;
    #pragma unroll
    for (int f = 0; f < NF; f++) {
        float u = W3[f];
        int off = f * NT;
        a0 += u * xb[b0 + off];
        a1 += u * xb[b1 + off];
        a2 += u * xb[b2 + off];
    }
    float* o = g_rhs_s + (size_t)b * NT * NN;
    o[t_0 * NN + m0 + m_0] = a0;
    o[t_1 * NN + m0 + m_1] = a1;
    o[t_2 * NN + m0 + m_2] = a2;
}

// ---------------------------------------------------------------------------
// K8: S_pre[b,n,m] = sum_t lhs2s[b,n,t]*rhs_s[b,t,m]    grid(16,16,NB) x 256
// ---------------------------------------------------------------------------
__global__ void __launch_bounds__(256) k_spre() {
    int b = blockIdx.z;
    int mtile = blockIdx.x * 64;
    int ntile = blockIdx.y * 64;
    __shared__ __align__(16) float Ls[64 * 25];
    __shared__ __align__(16) float Rs[24 * 64];
    int tid = threadIdx.x;
    const float* L = g_lhs2s + (size_t)b * NN * NT;
    const float* R = g_rhs_s + (size_t)b * NT * NN;
    #pragma unroll
    for (int i = 0; i < 6; i++) {
        int e = tid + i * 256;  // 1536
        int nn = e / 24, tt = e - nn * 24;
        Ls[nn * 25 + tt] = L[(size_t)(ntile + nn) * NT + tt];
        int t2 = e >> 6, m2 = e & 63;
        Rs[e] = R[(size_t)t2 * NN + mtile + m2];
    }
    __syncthreads();
    int tx = tid & 15, ty = tid >> 4;
    float acc[4][4];
    #pragma unroll
    for (int i = 0; i < 4; i++)
        #pragma unroll
        for (int j = 0; j < 4; j++) acc[i][j] = 0.f;
    #pragma unroll
    for (int kk = 0; kk < NT; kk++) {
        float a[4], bb[4];
        #pragma unroll
        for (int i = 0; i < 4; i++) a[i] = Ls[(ty * 4 + i) * 25 + kk];
        float4 rv = *(const float4*)&Rs[kk * 64 + tx * 4];
        bb[0] = rv.x; bb[1] = rv.y; bb[2] = rv.z; bb[3] = rv.w;
        #pragma unroll
        for (int i = 0; i < 4; i++)
            #pragma unroll
            for (int j = 0; j < 4; j++) acc[i][j] += a[i] * bb[j];
    }
    float* S = g_Spre + (size_t)b * NN * NN;
    #pragma unroll
    for (int i = 0; i < 4; i++) {
        float4 o;
        o.x = acc[i][0]; o.y = acc[i][1]; o.z = acc[i][2]; o.w = acc[i][3];
        *(float4*)&S[(size_t)(ntile + ty * 4 + i) * NN + mtile + tx * 4] = o;
    }
}

// ---------------------------------------------------------------------------
// K9: colmax over n of S_pre                            grid(NN/32,NB) x 256
// ---------------------------------------------------------------------------
__global__ void __launch_bounds__(256) k_cmax() {
    int b = blockIdx.y, m0 = blockIdx.x * 32;
    int tid = threadIdx.x, w = tid >> 5, lane = tid & 31;
    const float* S = g_Spre + (size_t)b * NN * NN;
    float mx = -3.4e38f;
    for (int n = w; n < NN; n += 8)
        mx = fmaxf(mx, S[(size_t)n * NN + m0 + lane]);
    __shared__ float red[8][32];
    red[w][lane] = mx;
    __syncthreads();
    if (w == 0) {
        float v = red[0][lane];
        #pragma unroll
        for (int i = 1; i < 8; i++) v = fmaxf(v, red[i][lane]);
        g_cmax[b * NN + m0 + lane] = v;
    }
}

// ---------------------------------------------------------------------------
// K10: Sexp = exp(S_pre - colmax), csum = colsum        grid(NN/32,NB) x 256
// ---------------------------------------------------------------------------
__global__ void __launch_bounds__(256) k_sexp() {
    int b = blockIdx.y, m0 = blockIdx.x * 32;
    int tid = threadIdx.x, w = tid >> 5, lane = tid & 31;
    const float* S = g_Spre + (size_t)b * NN * NN;
    float* E = g_Sexp + (size_t)b * NN * NN;
    float mx = g_cmax[b * NN + m0 + lane];
    float s = 0.f;
    for (int n = w; n < NN; n += 8) {
        size_t i = (size_t)n * NN + m0 + lane;
        float v = __expf(S[i] - mx);
        E[i] = v;
        s += v;
    }
    __shared__ float red[8][32];
    red[w][lane] = s;
    __syncthreads();
    if (w == 0) {
        float v = red[0][lane];
        #pragma unroll
        for (int i = 1; i < 8; i++) v += red[i][lane];
        g_csum[b * NN + m0 + lane] = v;
    }
}

// ---------------------------------------------------------------------------
// K11 (dominant): rhs_all[k,b,m,ft] =
//     (1/csum[b,m]) * sum_n cheb[k,n,m]*Sexp[b,n,m]*x[b,n,ft]
//   Tiles: BM=128 (m), BN=64 (ft), BK=16 (n). 256 threads, f32x2 packed FMA.
//   grid(12, 8, NB*NK) with z = b*NK + k (b-major for L2 residency)
// ---------------------------------------------------------------------------
__global__ void __launch_bounds__(256) k_gemm(const float* __restrict__ cheb,
                                              const float* __restrict__ x) {
    int kb = blockIdx.z;
    int b = kb / NK, k = kb - b * NK;
    int m0 = blockIdx.y * 128;
    int j0 = blockIdx.x * 64;
    const float* __restrict__ A1 = cheb + (size_t)k * NN * NN;
    const float* __restrict__ A2 = g_Sexp + (size_t)b * NN * NN;
    const float* __restrict__ xb = x + (size_t)b * NN * FT;
    __shared__ __align__(16) float As[16][128];
    __shared__ __align__(16) float Xs[16][64];
    int tid = threadIdx.x;
    int tx = tid & 15, ty = tid >> 4;  // tx: 16 ft-groups of 4, ty: 16 m-groups of 8
    unsigned long long acc[4][4];
    #pragma unroll
    for (int p = 0; p < 4; p++)
        #pragma unroll
        for (int c = 0; c < 4; c++) acc[p][c] = 0ull;

    for (int n0 = 0; n0 < NN; n0 += 16) {
        #pragma unroll
        for (int i = 0; i < 8; i++) {
            int e = tid + i * 256;
            int nn = e >> 7, mm = e & 127;
            size_t gi = (size_t)(n0 + nn) * NN + m0 + mm;
            As[nn][mm] = A1[gi] * A2[gi];
        }
        #pragma unroll
        for (int i = 0; i < 4; i++) {
            int e = tid + i * 256;
            int nn = e >> 6, jj = e & 63;
            Xs[nn][jj] = xb[(size_t)(n0 + nn) * FT + j0 + jj];
        }
        __syncthreads();
        #pragma unroll
        for (int kk = 0; kk < 16; kk++) {
            unsigned long long a0 = *(const unsigned long long*)&As[kk][ty * 8 + 0];
            unsigned long long a1 = *(const unsigned long long*)&As[kk][ty * 8 + 2];
            unsigned long long a2 = *(const unsigned long long*)&As[kk][ty * 8 + 4];
            unsigned long long a3 = *(const unsigned long long*)&As[kk][ty * 8 + 6];
            float4 xv = *(const float4*)&Xs[kk][tx * 4];
            unsigned long long x0 = pack2(xv.x), x1 = pack2(xv.y);
            unsigned long long x2 = pack2(xv.z), x3 = pack2(xv.w);
            ffma2(acc[0][0], a0, x0); ffma2(acc[0][1], a0, x1);
            ffma2(acc[0][2], a0, x2); ffma2(acc[0][3], a0, x3);
            ffma2(acc[1][0], a1, x0); ffma2(acc[1][1], a1, x1);
            ffma2(acc[1][2], a1, x2); ffma2(acc[1][3], a1, x3);
            ffma2(acc[2][0], a2, x0); ffma2(acc[2][1], a2, x1);
            ffma2(acc[2][2], a2, x2); ffma2(acc[2][3], a2, x3);
            ffma2(acc[3][0], a3, x0); ffma2(acc[3][1], a3, x1);
            ffma2(acc[3][2], a3, x2); ffma2(acc[3][3], a3, x3);
        }
        __syncthreads();
    }
    float inv[8];
    #pragma unroll
    for (int i = 0; i < 8; i++) inv[i] = 1.0f / g_csum[b * NN + m0 + ty * 8 + i];
    float* outBase = g_rhs_all + (size_t)(k * NB + b) * NN * FT;
    #pragma unroll
    for (int p = 0; p < 4; p++) {
        int r0 = m0 + ty * 8 + 2 * p;
        float4 o0, o1;
        o0.x = lo32(acc[p][0]) * inv[2 * p];
        o0.y = lo32(acc[p][1]) * inv[2 * p];
        o0.z = lo32(acc[p][2]) * inv[2 * p];
        o0.w = lo32(acc[p][3]) * inv[2 * p];
        o1.x = hi32(acc[p][0]) * inv[2 * p + 1];
        o1.y = hi32(acc[p][1]) * inv[2 * p + 1];
        o1.z = hi32(acc[p][2]) * inv[2 * p + 1];
        o1.w = hi32(acc[p][3]) * inv[2 * p + 1];
        *(float4*)&outBase[(size_t)r0 * FT + j0 + tx * 4] = o0;
        *(float4*)&outBase[(size_t)(r0 + 1) * FT + j0 + tx * 4] = o1;
    }
}

// ---------------------------------------------------------------------------
// K12: fused tail. Per (b, 8 nodes):
//   sg[m,o,t]  = relu(sum_{k,f} rhs_all[k,b,m,f,t] * Theta[k,f,o])
//   tco[m,c,t] = sum_cc sum_{r} sg[m,cc,t+r-1]*tc_w[c,cc,r] + tc_b[c]
//   res[m,c,t] = sum_f x[b,m,f,t]*rc_w[c,f] + rc_b[c]
//   z = relu(tco+res); LayerNorm over c; out[b,m,c,t]
//   grid(NN/8, NB) x 256, 205 KB dynamic smem
// ---------------------------------------------------------------------------
constexpr int TAIL_SMEM_FLOATS = 6144 + 12288 + 2048 + 4 * 64 + 8 * 64 * 26 + 8 * 3 * 768;
// = 6144+12288+2048+256+13312+18432 = 52480 floats = 209920 bytes

__global__ void __launch_bounds__(256) k_tail(
    const float* __restrict__ x, const float* __restrict__ Theta,
    const float* __restrict__ tcw, const float* __restrict__ tcb,
    const float* __restrict__ rcw, const float* __restrict__ rcb,
    const float* __restrict__ gma, const float* __restrict__ bet,
    float* __restrict__ out) {
    extern __shared__ float smf[];
    float* Th = smf;               // [k][f][o]  6144
    float* Wc = Th + 6144;         // [ct][cc][r] 12288
    float* Wr = Wc + 12288;        // [ct][f]   2048
    float* Bc = Wr + 2048;         // 64
    float* Br = Bc + 64;
    float* Ga = Br + 64;
    float* Be = Ga + 64;
    float* SG = Be + 64;           // [m][o][26] 13312 (t padded: slot t+1)
    float* BUF = SG + 13312;       // rhsS [m][k][768]=18432, reused: xS 6144 + z 12288

    int b = blockIdx.y, m0 = blockIdx.x * 8;
    int tid = threadIdx.x;
    for (int i = tid; i < 6144; i += 256) Th[i] = Theta[i];
    for (int i = tid; i < 12288; i += 256) Wc[i] = tcw[i];
    for (int i = tid; i < 2048; i += 256) Wr[i] = rcw[i];
    if (tid < 64) { Bc[tid] = tcb[tid]; Br[tid] = rcb[tid]; Ga[tid] = gma[tid]; Be[tid] = bet[tid]; }
    for (int i = tid; i < 13312; i += 256) SG[i] = 0.f;
    for (int e = tid; e < 18432; e += 256) {
        int m = e / 2304, r = e - m * 2304;
        int k = r / 768, ft = r - k * 768;
        BUF[e] = g_rhs_all[((size_t)(k * NB + b) * NN + m0 + m) * FT + ft];
    }
    __syncthreads();

    // sg = relu(Theta contraction)
    for (int idx = tid; idx < 8 * 64 * NT; idx += 256) {
        int m = idx / (64 * NT), r = idx - m * (64 * NT);
        int o = r / NT, t = r - o * NT;
        const float* bm = &BUF[m * 2304 + t];
        float s = 0.f;
        #pragma unroll
        for (int k = 0; k < NK; k++) {
            const float* bk = bm + k * 768;
            const float* th = &Th[k * 2048 + o];
            #pragma unroll
            for (int f = 0; f < NF; f++) s += bk[f * NT] * th[f * 64];
        }
        SG[(m * 64 + o) * 26 + t + 1] = fmaxf(s, 0.f);
    }
    __syncthreads();

    // stage x rows (overwrites rhs staging)
    for (int e = tid; e < 6144; e += 256) {
        int m = e / 768, ft = e - m * 768;
        BUF[e] = x[((size_t)(b * NN + m0 + m)) * FT + ft];
    }
    __syncthreads();

    // z = relu(timeconv + residual)
    for (int idx = tid; idx < 8 * 64 * NT; idx += 256) {
        int m = idx / (64 * NT), r = idx - m * (64 * NT);
        int ct = r / NT, t = r - ct * NT;
        const float* w = &Wc[ct * 192];
        const float* sgm = &SG[m * 1664 + t];  // sgm[cc*26 + dt]: dt0=t-1,1=t,2=t+1
        float s = Bc[ct];
        #pragma unroll 8
        for (int cc = 0; cc < NCC; cc++) {
            const float* sr = sgm + cc * 26;
            s += sr[0] * w[cc * 3] + sr[1] * w[cc * 3 + 1] + sr[2] * w[cc * 3 + 2];
        }
        float rres = Br[ct];
        const float* xm = &BUF[m * 768 + t];
        const float* wr = &Wr[ct * 32];
        #pragma unroll
        for (int f = 0; f < NF; f++) rres += xm[f * NT] * wr[f];
        BUF[6144 + idx] = fmaxf(s + rres, 0.f);
    }
    __syncthreads();

    // LayerNorm over ct, write out[b,m,ct,t]
    for (int p = tid; p < 8 * NT; p += 256) {
        int m = p / NT, t = p - m * NT;
        const float* zz = &BUF[6144 + m * (64 * NT) + t];
        float mu = 0.f;
        #pragma unroll
        for (int c = 0; c < NCT; c++) mu += zz[c * NT];
        mu *= (1.f / 64.f);
        float var = 0.f;
        #pragma unroll
        for (int c = 0; c < NCT; c++) { float d = zz[c * NT] - mu; var += d * d; }
        var *= (1.f / 64.f);
        float rs = rsqrtf(var + 1e-5f);
        float* op = out + ((size_t)(b * NN + m0 + m) * NCT) * NT + t;
        #pragma unroll
        for (int c = 0; c < NCT; c++)
            op[c * NT] = (zz[c * NT] - mu) * rs * Ga[c] + Be[c];
    }
}

// ---------------------------------------------------------------------------
extern "C" void kernel_launch(void* const* d_in, const int* in_sizes, int n_in,
                              void* d_out, int out_size) {
    const float* x     = (const float*)d_in[0];
    const float* W1    = (const float*)d_in[1];
    const float* W2    = (const float*)d_in[2];
    const float* W3    = (const float*)d_in[3];
    const float* U1    = (const float*)d_in[4];
    const float* U2    = (const float*)d_in[5];
    const float* U3    = (const float*)d_in[6];
    const float* cheb  = (const float*)d_in[7];
    const float* Theta = (const float*)d_in[8];
    const float* tc_w  = (const float*)d_in[9];
    const float* tc_b  = (const float*)d_in[10];
    const float* rc_w  = (const float*)d_in[11];
    const float* rc_b  = (const float*)d_in[12];
    const float* gamma = (const float*)d_in[13];
    const float* beta  = (const float*)d_in[14];
    float* out = (float*)d_out;

    cudaFuncSetAttribute(k_tail, cudaFuncAttributeMaxDynamicSharedMemorySize,
                         TAIL_SMEM_FLOATS * 4);

    // temporal attention
    k_lhs_t<<<dim3(NT, NB), 256>>>(x, U1);
    k_rhs_t<<<dim3(NN / 32, NB), 256>>>(x, U3);
    k_epre<<<dim3(NT, NB), 256>>>(U2);
    k_esm<<<dim3(NT, NB), 32>>>();
    k_xtat<<<NB * 128, 256>>>(x);
    // spatial attention
    k_lhs2s<<<NB * 128, 256>>>(W1, W2);
    k_rhs_s<<<dim3(NN / 32, NB), 256>>>(W3);
    k_spre<<<dim3(16, 16, NB), 256>>>();
    k_cmax<<<dim3(NN / 32, NB), 256>>>();
    k_sexp<<<dim3(NN / 32, NB), 256>>>();
    // chebyshev graph conv (dominant)
    k_gemm<<<dim3(12, 8, NB * NK), 256>>>(cheb, x);
    // fused Theta + timeconv + residual + LN
    k_tail<<<dim3(NN / 8, NB), 256, TAIL_SMEM_FLOATS * 4>>>(
        x, Theta, tc_w, tc_b, rc_w, rc_b, gamma, beta, out);
}

// round 7
// speedup vs baseline: 1.0566x; 1.0566x over previous
#include <cuda_runtime.h>
#include <cuda_bf16.h>
#include <cstdint>
#include <cstddef>

// ---------------------------------------------------------------------------
// ASTGCN block, fp32.  Shapes: B=16, N=1024, F=32, T=24, K=3, CC=CT=64.
// ---------------------------------------------------------------------------

constexpr int NB  = 16;
constexpr int NN  = 1024;
constexpr int NF  = 32;
constexpr int NT  = 24;
constexpr int NK  = 3;
constexpr int NCC = 64;
constexpr int NCT = 64;
constexpr int FT  = NF * NT;   // 768

// ------------------------- scratch (device globals) ------------------------
__device__ float g_lhs_t[NB * NT * NF];
__device__ float g_rhs_t[NB * NN * NT];
__device__ float g_Epre[NB * NT * NT];
__device__ float g_E[NB * NT * NT];
__device__ float g_xTAt[(size_t)NB * NN * FT];
__device__ float g_lhs2s[NB * NN * NT];
__device__ float g_rhs_s[NB * NT * NN];
__device__ float g_Spre[(size_t)NB * NN * NN];
__device__ float g_cmax[NB * NN];
__device__ float g_Sexp[(size_t)NB * NN * NN];
__device__ float g_csum[NB * NN];
__device__ float g_rhs_all[(size_t)NK * NB * NN * FT];

// ------------------------------ helpers ------------------------------------
__device__ __forceinline__ void ffma2(unsigned long long& d,
                                      unsigned long long a,
                                      unsigned long long b) {
    asm("fma.rn.f32x2 %0, %1, %2, %0;" : "+l"(d) : "l"(a), "l"(b));
}
__device__ __forceinline__ unsigned long long pack2(float x) {
    unsigned long long r;
    asm("mov.b64 %0, {%1, %1};" : "=l"(r) : "f"(x));
    return r;
}
__device__ __forceinline__ float lo32(unsigned long long v) {
    return __uint_as_float((unsigned)(v & 0xffffffffull));
}
__device__ __forceinline__ float hi32(unsigned long long v) {
    return __uint_as_float((unsigned)(v >> 32));
}

// ---------------------------------------------------------------------------
// K1: lhs_t[b,t,f] = sum_n x[b,n,f,t] * U1[n]           grid(NT,NB) x 256
// ---------------------------------------------------------------------------
__global__ void __launch_bounds__(256) k_lhs_t(const float* __restrict__ x,
                                               const float* __restrict__ U1) {
    int t = blockIdx.x, b = blockIdx.y;
    int w = threadIdx.x >> 5, lane = threadIdx.x & 31;
    const float* xb = x + (size_t)b * NN * FT;
    for (int f = w; f < NF; f += 8) {
        float s = 0.f;
        for (int n = lane; n < NN; n += 32)
            s += xb[(size_t)n * FT + f * NT + t] * U1[n];
        #pragma unroll
        for (int o = 16; o; o >>= 1) s += __shfl_xor_sync(0xffffffffu, s, o);
        if (lane == 0) g_lhs_t[(b * NT + t) * NF + f] = s;
    }
}

// ---------------------------------------------------------------------------
// K2: rhs_t[b,n,t] = sum_f U3[f] * x[b,n,f,t]           grid(NN/32,NB) x 256
// ---------------------------------------------------------------------------
__global__ void __launch_bounds__(256) k_rhs_t(const float* __restrict__ x,
                                               const float* __restrict__ U3) {
    int b = blockIdx.y, n0 = blockIdx.x * 32;
    int tid = threadIdx.x;
    const float* xb = x + (size_t)b * NN * FT;
    int e0 = tid, e1 = tid + 256, e2 = tid + 512;  // over 32n x 24t = 768
    size_t b0 = (size_t)(n0 + e0 / 24) * FT + (e0 % 24);
    size_t b1 = (size_t)(n0 + e1 / 24) * FT + (e1 % 24);
    size_t b2 = (size_t)(n0 + e2 / 24) * FT + (e2 % 24);
    float a0 = 0.f, a1 = 0.f, a2 = 0.f;
    #pragma unroll
    for (int f = 0; f < NF; f++) {
        float u = U3[f];
        int off = f * NT;
        a0 += u * xb[b0 + off];
        a1 += u * xb[b1 + off];
        a2 += u * xb[b2 + off];
    }
    float* o = g_rhs_t + (size_t)b * NN * NT + (size_t)n0 * NT;
    o[e0] = a0; o[e1] = a1; o[e2] = a2;
}

// ---------------------------------------------------------------------------
// K3: E_pre[b,t,s] = sum_n (sum_f lhs_t[b,t,f]U2[f,n]) * rhs_t[b,n,s]
//                                                        grid(NT,NB) x 256
// ---------------------------------------------------------------------------
__global__ void __launch_bounds__(256) k_epre(const float* __restrict__ U2) {
    int t = blockIdx.x, b = blockIdx.y;
    __shared__ float lt[NF];
    __shared__ float red[8][NT];
    int tid = threadIdx.x;
    if (tid < NF) lt[tid] = g_lhs_t[(b * NT + t) * NF + tid];
    __syncthreads();
    float pe[NT];
    #pragma unroll
    for (int s = 0; s < NT; s++) pe[s] = 0.f;
    for (int n = tid; n < NN; n += 256) {
        float l2 = 0.f;
        #pragma unroll
        for (int f = 0; f < NF; f++) l2 += lt[f] * U2[f * NN + n];
        const float* rr = &g_rhs_t[((size_t)b * NN + n) * NT];
        #pragma unroll
        for (int s = 0; s < NT; s++) pe[s] += l2 * rr[s];
    }
    int lane = tid & 31, w = tid >> 5;
    #pragma unroll
    for (int s = 0; s < NT; s++) {
        float v = pe[s];
        #pragma unroll
        for (int o = 16; o; o >>= 1) v += __shfl_xor_sync(0xffffffffu, v, o);
        if (lane == 0) red[w][s] = v;
    }
    __syncthreads();
    if (tid < NT) {
        float v = 0.f;
        #pragma unroll
        for (int w2 = 0; w2 < 8; w2++) v += red[w2][tid];
        g_Epre[b * NT * NT + t * NT + tid] = v;
    }
}

// ---------------------------------------------------------------------------
// K4: E = softmax(E_pre, axis=t)   one warp per (b,s)    grid(NT,NB) x 32
// ---------------------------------------------------------------------------
__global__ void k_esm() {
    int s = blockIdx.x, b = blockIdx.y, lane = threadIdx.x;
    float v = (lane < NT) ? g_Epre[b * NT * NT + lane * NT + s] : -3.4e38f;
    float mx = v;
    #pragma unroll
    for (int o = 16; o; o >>= 1) mx = fmaxf(mx, __shfl_xor_sync(0xffffffffu, mx, o));
    float e = (lane < NT) ? __expf(v - mx) : 0.f;
    float sm = e;
    #pragma unroll
    for (int o = 16; o; o >>= 1) sm += __shfl_xor_sync(0xffffffffu, sm, o);
    if (lane < NT) g_E[b * NT * NT + lane * NT + s] = e / sm;
}

// ---------------------------------------------------------------------------
// K5: x_TAt[b,n,f,s] = sum_t x[b,n,f,t]*E[b,t,s]        grid(NB*128) x 256
// ---------------------------------------------------------------------------
__global__ void __launch_bounds__(256) k_xtat(const float* __restrict__ x) {
    int b = blockIdx.x >> 7;  // 128 blocks per b
    size_t row = (size_t)blockIdx.x * 256 + threadIdx.x;  // (b,n,f) row
    __shared__ float Es[NT * NT];
    for (int i = threadIdx.x; i < NT * NT; i += 256) Es[i] = g_E[b * NT * NT + i];
    __syncthreads();
    float in[NT];
    const float4* ip = (const float4*)(x + row * NT);
    #pragma unroll
    for (int i = 0; i < 6; i++) ((float4*)in)[i] = ip[i];
    float o[NT];
    #pragma unroll
    for (int s = 0; s < NT; s++) {
        float a = 0.f;
        #pragma unroll
        for (int t = 0; t < NT; t++) a += in[t] * Es[t * NT + s];
        o[s] = a;
    }
    float4* op = (float4*)(g_xTAt + row * NT);
    #pragma unroll
    for (int i = 0; i < 6; i++) op[i] = ((float4*)o)[i];
}

// ---------------------------------------------------------------------------
// K6: lhs2s[b,n,t] = sum_f (sum_t' xTAt[b,n,f,t']W1[t']) * W2[f,t]
//                                                        grid(NB*128) x 256
// ---------------------------------------------------------------------------
__global__ void __launch_bounds__(256) k_lhs2s(const float* __restrict__ W1,
                                               const float* __restrict__ W2) {
    int bb = blockIdx.x;
    int b = bb >> 7;
    int n0 = (bb & 127) * 8;
    __shared__ float ls[8][NF];
    int tid = threadIdx.x;
    int ni = tid >> 5, f = tid & 31;
    const float* r = g_xTAt + ((size_t)(b * NN + n0 + ni) * NF + f) * NT;
    float s = 0.f;
    #pragma unroll
    for (int t = 0; t < NT; t++) s += r[t] * W1[t];
    ls[ni][f] = s;
    __syncthreads();
    if (tid < 8 * NT) {
        int ni2 = tid / NT, t = tid - ni2 * NT;
        float v = 0.f;
        #pragma unroll
        for (int ff = 0; ff < NF; ff++) v += ls[ni2][ff] * W2[ff * NT + t];
        g_lhs2s[((size_t)b * NN + n0 + ni2) * NT + t] = v;
    }
}

// ---------------------------------------------------------------------------
// K7: rhs_s[b,t,m] = sum_f W3[f] * xTAt[b,m,f,t]        grid(NN/32,NB) x 256
// ---------------------------------------------------------------------------
__global__ void __launch_bounds__(256) k_rhs_s(const float* __restrict__ W3) {
    int b = blockIdx.y, m0 = blockIdx.x * 32;
    int tid = threadIdx.x;
    const float* xb = g_xTAt + (size_t)b * NN * FT;
    int e0 = tid, e1 = tid + 256, e2 = tid + 512;  // 32m x 24t
    int m_0 = e0 / 24, t_0 = e0 - m_0 * 24;
    int m_1 = e1 / 24, t_1 = e1 - m_1 * 24;
    int m_2 = e2 / 24, t_2 = e2 - m_2 * 24;
    size_t b0 = (size_t)(m0 + m_0) * FT + t_0;
    size_t b1 = (size_t)(m0 + m_1) * FT + t_1;
    size_t b2 = (size_t)(m0 + m_2) * FT + t_2;
    float a0 = 0.f, a1 = 0.f, a2 = 0.f;
    #pragma unroll
    for (int f = 0; f < NF; f++) {
        float u = W3[f];
        int off = f * NT;
        a0 += u * xb[b0 + off];
        a1 += u * xb[b1 + off];
        a2 += u * xb[b2 + off];
    }
    float* o = g_rhs_s + (size_t)b * NT * NN;
    o[t_0 * NN + m0 + m_0] = a0;
    o[t_1 * NN + m0 + m_1] = a1;
    o[t_2 * NN + m0 + m_2] = a2;
}

// ---------------------------------------------------------------------------
// K8: S_pre[b,n,m] = sum_t lhs2s[b,n,t]*rhs_s[b,t,m]    grid(16,16,NB) x 256
// ---------------------------------------------------------------------------
__global__ void __launch_bounds__(256) k_spre() {
    int b = blockIdx.z;
    int mtile = blockIdx.x * 64;
    int ntile = blockIdx.y * 64;
    __shared__ __align__(16) float Ls[64 * 25];
    __shared__ __align__(16) float Rs[24 * 64];
    int tid = threadIdx.x;
    const float* L = g_lhs2s + (size_t)b * NN * NT;
    const float* R = g_rhs_s + (size_t)b * NT * NN;
    #pragma unroll
    for (int i = 0; i < 6; i++) {
        int e = tid + i * 256;  // 1536
        int nn = e / 24, tt = e - nn * 24;
        Ls[nn * 25 + tt] = L[(size_t)(ntile + nn) * NT + tt];
        int t2 = e >> 6, m2 = e & 63;
        Rs[e] = R[(size_t)t2 * NN + mtile + m2];
    }
    __syncthreads();
    int tx = tid & 15, ty = tid >> 4;
    float acc[4][4];
    #pragma unroll
    for (int i = 0; i < 4; i++)
        #pragma unroll
        for (int j = 0; j < 4; j++) acc[i][j] = 0.f;
    #pragma unroll
    for (int kk = 0; kk < NT; kk++) {
        float a[4], bb[4];
        #pragma unroll
        for (int i = 0; i < 4; i++) a[i] = Ls[(ty * 4 + i) * 25 + kk];
        float4 rv = *(const float4*)&Rs[kk * 64 + tx * 4];
        bb[0] = rv.x; bb[1] = rv.y; bb[2] = rv.z; bb[3] = rv.w;
        #pragma unroll
        for (int i = 0; i < 4; i++)
            #pragma unroll
            for (int j = 0; j < 4; j++) acc[i][j] += a[i] * bb[j];
    }
    float* S = g_Spre + (size_t)b * NN * NN;
    #pragma unroll
    for (int i = 0; i < 4; i++) {
        float4 o;
        o.x = acc[i][0]; o.y = acc[i][1]; o.z = acc[i][2]; o.w = acc[i][3];
        *(float4*)&S[(size_t)(ntile + ty * 4 + i) * NN + mtile + tx * 4] = o;
    }
}

// ---------------------------------------------------------------------------
// K9: colmax over n of S_pre                            grid(NN/32,NB) x 256
// ---------------------------------------------------------------------------
__global__ void __launch_bounds__(256) k_cmax() {
    int b = blockIdx.y, m0 = blockIdx.x * 32;
    int tid = threadIdx.x, w = tid >> 5, lane = tid & 31;
    const float* S = g_Spre + (size_t)b * NN * NN;
    float mx = -3.4e38f;
    for (int n = w; n < NN; n += 8)
        mx = fmaxf(mx, S[(size_t)n * NN + m0 + lane]);
    __shared__ float red[8][32];
    red[w][lane] = mx;
    __syncthreads();
    if (w == 0) {
        float v = red[0][lane];
        #pragma unroll
        for (int i = 1; i < 8; i++) v = fmaxf(v, red[i][lane]);
        g_cmax[b * NN + m0 + lane] = v;
    }
}

// ---------------------------------------------------------------------------
// K10: Sexp = exp(S_pre - colmax), csum = colsum        grid(NN/32,NB) x 256
// ---------------------------------------------------------------------------
__global__ void __launch_bounds__(256) k_sexp() {
    int b = blockIdx.y, m0 = blockIdx.x * 32;
    int tid = threadIdx.x, w = tid >> 5, lane = tid & 31;
    const float* S = g_Spre + (size_t)b * NN * NN;
    float* E = g_Sexp + (size_t)b * NN * NN;
    float mx = g_cmax[b * NN + m0 + lane];
    float s = 0.f;
    for (int n = w; n < NN; n += 8) {
        size_t i = (size_t)n * NN + m0 + lane;
        float v = __expf(S[i] - mx);
        E[i] = v;
        s += v;
    }
    __shared__ float red[8][32];
    red[w][lane] = s;
    __syncthreads();
    if (w == 0) {
        float v = red[0][lane];
        #pragma unroll
        for (int i = 1; i < 8; i++) v += red[i][lane];
        g_csum[b * NN + m0 + lane] = v;
    }
}

// ---------------------------------------------------------------------------
// K11 (dominant): rhs_all[k,b,m,ft] =
//     (1/csum[b,m]) * sum_n cheb[k,n,m]*Sexp[b,n,m]*x[b,n,ft]
//   Tiles: BM=128 (m), BN=64 (ft), BK=16 (n). 256 threads, f32x2 packed FMA.
//   grid(12, 8, NB*NK) with z = b*NK + k (b-major for L2 residency)
// ---------------------------------------------------------------------------
__global__ void __launch_bounds__(256) k_gemm(const float* __restrict__ cheb,
                                              const float* __restrict__ x) {
    int kb = blockIdx.z;
    int b = kb / NK, k = kb - b * NK;
    int m0 = blockIdx.y * 128;
    int j0 = blockIdx.x * 64;
    const float* __restrict__ A1 = cheb + (size_t)k * NN * NN;
    const float* __restrict__ A2 = g_Sexp + (size_t)b * NN * NN;
    const float* __restrict__ xb = x + (size_t)b * NN * FT;
    __shared__ __align__(16) float As[16][128];
    __shared__ __align__(16) float Xs[16][64];
    int tid = threadIdx.x;
    int tx = tid & 15, ty = tid >> 4;  // tx: 16 ft-groups of 4, ty: 16 m-groups of 8
    unsigned long long acc[4][4];
    #pragma unroll
    for (int p = 0; p < 4; p++)
        #pragma unroll
        for (int c = 0; c < 4; c++) acc[p][c] = 0ull;

    for (int n0 = 0; n0 < NN; n0 += 16) {
        #pragma unroll
        for (int i = 0; i < 8; i++) {
            int e = tid + i * 256;
            int nn = e >> 7, mm = e & 127;
            size_t gi = (size_t)(n0 + nn) * NN + m0 + mm;
            As[nn][mm] = A1[gi] * A2[gi];
        }
        #pragma unroll
        for (int i = 0; i < 4; i++) {
            int e = tid + i * 256;
            int nn = e >> 6, jj = e & 63;
            Xs[nn][jj] = xb[(size_t)(n0 + nn) * FT + j0 + jj];
        }
        __syncthreads();
        #pragma unroll
        for (int kk = 0; kk < 16; kk++) {
            unsigned long long a0 = *(const unsigned long long*)&As[kk][ty * 8 + 0];
            unsigned long long a1 = *(const unsigned long long*)&As[kk][ty * 8 + 2];
            unsigned long long a2 = *(const unsigned long long*)&As[kk][ty * 8 + 4];
            unsigned long long a3 = *(const unsigned long long*)&As[kk][ty * 8 + 6];
            float4 xv = *(const float4*)&Xs[kk][tx * 4];
            unsigned long long x0 = pack2(xv.x), x1 = pack2(xv.y);
            unsigned long long x2 = pack2(xv.z), x3 = pack2(xv.w);
            ffma2(acc[0][0], a0, x0); ffma2(acc[0][1], a0, x1);
            ffma2(acc[0][2], a0, x2); ffma2(acc[0][3], a0, x3);
            ffma2(acc[1][0], a1, x0); ffma2(acc[1][1], a1, x1);
            ffma2(acc[1][2], a1, x2); ffma2(acc[1][3], a1, x3);
            ffma2(acc[2][0], a2, x0); ffma2(acc[2][1], a2, x1);
            ffma2(acc[2][2], a2, x2); ffma2(acc[2][3], a2, x3);
            ffma2(acc[3][0], a3, x0); ffma2(acc[3][1], a3, x1);
            ffma2(acc[3][2], a3, x2); ffma2(acc[3][3], a3, x3);
        }
        __syncthreads();
    }
    float inv[8];
    #pragma unroll
    for (int i = 0; i < 8; i++) inv[i] = 1.0f / g_csum[b * NN + m0 + ty * 8 + i];
    float* outBase = g_rhs_all + (size_t)(k * NB + b) * NN * FT;
    #pragma unroll
    for (int p = 0; p < 4; p++) {
        int r0 = m0 + ty * 8 + 2 * p;
        float4 o0, o1;
        o0.x = lo32(acc[p][0]) * inv[2 * p];
        o0.y = lo32(acc[p][1]) * inv[2 * p];
        o0.z = lo32(acc[p][2]) * inv[2 * p];
        o0.w = lo32(acc[p][3]) * inv[2 * p];
        o1.x = hi32(acc[p][0]) * inv[2 * p + 1];
        o1.y = hi32(acc[p][1]) * inv[2 * p + 1];
        o1.z = hi32(acc[p][2]) * inv[2 * p + 1];
        o1.w = hi32(acc[p][3]) * inv[2 * p + 1];
        *(float4*)&outBase[(size_t)r0 * FT + j0 + tx * 4] = o0;
        *(float4*)&outBase[(size_t)(r0 + 1) * FT + j0 + tx * 4] = o1;
    }
}

// ---------------------------------------------------------------------------
// K12: fused tail. Per (b, 8 nodes):
//   sg[m,o,t]  = relu(sum_{k,f} rhs_all[k,b,m,f,t] * Theta[k,f,o])
//   tco[m,c,t] = sum_cc sum_{r} sg[m,cc,t+r-1]*tc_w[c,cc,r] + tc_b[c]
//   res[m,c,t] = sum_f x[b,m,f,t]*rc_w[c,f] + rc_b[c]
//   z = relu(tco+res); LayerNorm over c; out[b,m,c,t]
//   grid(NN/8, NB) x 256, 205 KB dynamic smem
// ---------------------------------------------------------------------------
constexpr int TAIL_SMEM_FLOATS = 6144 + 12288 + 2048 + 4 * 64 + 8 * 64 * 26 + 8 * 3 * 768;
// = 6144+12288+2048+256+13312+18432 = 52480 floats = 209920 bytes

__global__ void __launch_bounds__(256) k_tail(
    const float* __restrict__ x, const float* __restrict__ Theta,
    const float* __restrict__ tcw, const float* __restrict__ tcb,
    const float* __restrict__ rcw, const float* __restrict__ rcb,
    const float* __restrict__ gma, const float* __restrict__ bet,
    float* __restrict__ out) {
    extern __shared__ float smf[];
    float* Th = smf;               // [k][f][o]  6144
    float* Wc = Th + 6144;         // [ct][cc][r] 12288
    float* Wr = Wc + 12288;        // [ct][f]   2048
    float* Bc = Wr + 2048;         // 64
    float* Br = Bc + 64;
    float* Ga = Br + 64;
    float* Be = Ga + 64;
    float* SG = Be + 64;           // [m][o][26] 13312 (t padded: slot t+1)
    float* BUF = SG + 13312;       // rhsS [m][k][768]=18432, reused: xS 6144 + z 12288

    int b = blockIdx.y, m0 = blockIdx.x * 8;
    int tid = threadIdx.x;
    for (int i = tid; i < 6144; i += 256) Th[i] = Theta[i];
    for (int i = tid; i < 12288; i += 256) Wc[i] = tcw[i];
    for (int i = tid; i < 2048; i += 256) Wr[i] = rcw[i];
    if (tid < 64) { Bc[tid] = tcb[tid]; Br[tid] = rcb[tid]; Ga[tid] = gma[tid]; Be[tid] = bet[tid]; }
    for (int i = tid; i < 13312; i += 256) SG[i] = 0.f;
    for (int e = tid; e < 18432; e += 256) {
        int m = e / 2304, r = e - m * 2304;
        int k = r / 768, ft = r - k * 768;
        BUF[e] = g_rhs_all[((size_t)(k * NB + b) * NN + m0 + m) * FT + ft];
    }
    __syncthreads();

    // sg = relu(Theta contraction)
    for (int idx = tid; idx < 8 * 64 * NT; idx += 256) {
        int m = idx / (64 * NT), r = idx - m * (64 * NT);
        int o = r / NT, t = r - o * NT;
        const float* bm = &BUF[m * 2304 + t];
        float s = 0.f;
        #pragma unroll
        for (int k = 0; k < NK; k++) {
            const float* bk = bm + k * 768;
            const float* th = &Th[k * 2048 + o];
            #pragma unroll
            for (int f = 0; f < NF; f++) s += bk[f * NT] * th[f * 64];
        }
        SG[(m * 64 + o) * 26 + t + 1] = fmaxf(s, 0.f);
    }
    __syncthreads();

    // stage x rows (overwrites rhs staging)
    for (int e = tid; e < 6144; e += 256) {
        int m = e / 768, ft = e - m * 768;
        BUF[e] = x[((size_t)(b * NN + m0 + m)) * FT + ft];
    }
    __syncthreads();

    // z = relu(timeconv + residual)
    for (int idx = tid; idx < 8 * 64 * NT; idx += 256) {
        int m = idx / (64 * NT), r = idx - m * (64 * NT);
        int ct = r / NT, t = r - ct * NT;
        const float* w = &Wc[ct * 192];
        const float* sgm = &SG[m * 1664 + t];  // sgm[cc*26 + dt]: dt0=t-1,1=t,2=t+1
        float s = Bc[ct];
        #pragma unroll 8
        for (int cc = 0; cc < NCC; cc++) {
            const float* sr = sgm + cc * 26;
            s += sr[0] * w[cc * 3] + sr[1] * w[cc * 3 + 1] + sr[2] * w[cc * 3 + 2];
        }
        float rres = Br[ct];
        const float* xm = &BUF[m * 768 + t];
        const float* wr = &Wr[ct * 32];
        #pragma unroll
        for (int f = 0; f < NF; f++) rres += xm[f * NT] * wr[f];
        BUF[6144 + idx] = fmaxf(s + rres, 0.f);
    }
    __syncthreads();

    // LayerNorm over ct, write out[b,m,ct,t]
    for (int p = tid; p < 8 * NT; p += 256) {
        int m = p / NT, t = p - m * NT;
        const float* zz = &BUF[6144 + m * (64 * NT) + t];
        float mu = 0.f;
        #pragma unroll
        for (int c = 0; c < NCT; c++) mu += zz[c * NT];
        mu *= (1.f / 64.f);
        float var = 0.f;
        #pragma unroll
        for (int c = 0; c < NCT; c++) { float d = zz[c * NT] - mu; var += d * d; }
        var *= (1.f / 64.f);
        float rs = rsqrtf(var + 1e-5f);
        float* op = out + ((size_t)(b * NN + m0 + m) * NCT) * NT + t;
        #pragma unroll
        for (int c = 0; c < NCT; c++)
            op[c * NT] = (zz[c * NT] - mu) * rs * Ga[c] + Be[c];
    }
}

// ---------------------------------------------------------------------------
extern "C" void kernel_launch(void* const* d_in, const int* in_sizes, int n_in,
                              void* d_out, int out_size) {
    const float* x     = (const float*)d_in[0];
    const float* W1    = (const float*)d_in[1];
    const float* W2    = (const float*)d_in[2];
    const float* W3    = (const float*)d_in[3];
    const float* U1    = (const float*)d_in[4];
    const float* U2    = (const float*)d_in[5];
    const float* U3    = (const float*)d_in[6];
    const float* cheb  = (const float*)d_in[7];
    const float* Theta = (const float*)d_in[8];
    const float* tc_w  = (const float*)d_in[9];
    const float* tc_b  = (const float*)d_in[10];
    const float* rc_w  = (const float*)d_in[11];
    const float* rc_b  = (const float*)d_in[12];
    const float* gamma = (const float*)d_in[13];
    const float* beta  = (const float*)d_in[14];
    float* out = (float*)d_out;

    cudaFuncSetAttribute(k_tail, cudaFuncAttributeMaxDynamicSharedMemorySize,
                         TAIL_SMEM_FLOATS * 4);

    // temporal attention
    k_lhs_t<<<dim3(NT, NB), 256>>>(x, U1);
    k_rhs_t<<<dim3(NN / 32, NB), 256>>>(x, U3);
    k_epre<<<dim3(NT, NB), 256>>>(U2);
    k_esm<<<dim3(NT, NB), 32>>>();
    k_xtat<<<NB * 128, 256>>>(x);
    // spatial attention
    k_lhs2s<<<NB * 128, 256>>>(W1, W2);
    k_rhs_s<<<dim3(NN / 32, NB), 256>>>(W3);
    k_spre<<<dim3(16, 16, NB), 256>>>();
    k_cmax<<<dim3(NN / 32, NB), 256>>>();
    k_sexp<<<dim3(NN / 32, NB), 256>>>();
    // chebyshev graph conv (dominant)
    k_gemm<<<dim3(12, 8, NB * NK), 256>>>(cheb, x);
    // fused Theta + timeconv + residual + LN
    k_tail<<<dim3(NN / 8, NB), 256, TAIL_SMEM_FLOATS * 4>>>(
        x, Theta, tc_w, tc_b, rc_w, rc_b, gamma, beta, out);
}

// round 9
// speedup vs baseline: 2.2015x; 2.0836x over previous
#include <cuda_runtime.h>
#include <cuda_bf16.h>
#include <cstdint>
#include <cstddef>

// ---------------------------------------------------------------------------
// ASTGCN block. B=16, N=1024, F=32, T=24, K=3, CC=CT=64.
// Cheb-GEMM on mma.sync bf16 (3-term compensated, fp32 accum) — works on
// plain sm_103 target (tcgen05 needs sm_103a which this toolchain rejects).
// ---------------------------------------------------------------------------

constexpr int NB  = 16;
constexpr int NN  = 1024;
constexpr int NF  = 32;
constexpr int NT  = 24;
constexpr int NK  = 3;
constexpr int NCC = 64;
constexpr int NCT = 64;
constexpr int FT  = NF * NT;   // 768

// ------------------------- scratch (device globals) ------------------------
__device__ float g_lpart[NB * 8 * FT];
__device__ float g_lhs_t[NB * NT * NF];
__device__ float g_rhs_t[NB * NN * NT];
__device__ float g_Epre[NB * NT * NT];
__device__ float g_E[NB * NT * NT];
__device__ float g_xTAt[(size_t)NB * NN * FT];
__device__ float g_lhs2s[NB * NN * NT];
__device__ float g_rhs_s[NB * NT * NN];
__device__ float g_Spre[(size_t)NB * NN * NN];
__device__ float g_cmax[NB * NN];
__device__ float g_Sexp[(size_t)NB * NN * NN];
__device__ float g_icsum[NB * NN];
__device__ __align__(16) unsigned short g_AT_hi[(size_t)NK * NB * NN * NN]; // [b*3+k][m][n]
__device__ __align__(16) unsigned short g_AT_lo[(size_t)NK * NB * NN * NN];
__device__ __align__(16) unsigned short g_XT_hi[(size_t)NB * FT * NN];      // [b][j][n]
__device__ __align__(16) unsigned short g_XT_lo[(size_t)NB * FT * NN];
__device__ float g_rhs_all[(size_t)NK * NB * NN * FT];  // [(k*NB+b)][m][ft]

// ------------------------------ helpers ------------------------------------
__device__ __forceinline__ uint32_t smem_u32(const void* p) {
    uint32_t a;
    asm("{ .reg .u64 t; cvta.to.shared.u64 t, %1; cvt.u32.u64 %0, t; }"
        : "=r"(a) : "l"(p));
    return a;
}
__device__ __forceinline__ void ffma2(unsigned long long& d,
                                      unsigned long long a,
                                      unsigned long long b) {
    asm("fma.rn.f32x2 %0, %1, %2, %0;" : "+l"(d) : "l"(a), "l"(b));
}
__device__ __forceinline__ unsigned long long pack2(float x) {
    unsigned long long r;
    asm("mov.b64 %0, {%1, %1};" : "=l"(r) : "f"(x));
    return r;
}
__device__ __forceinline__ float lo32(unsigned long long v) {
    return __uint_as_float((unsigned)(v & 0xffffffffull));
}
__device__ __forceinline__ float hi32(unsigned long long v) {
    return __uint_as_float((unsigned)(v >> 32));
}
__device__ __forceinline__ void ldmx4(uint32_t* r, uint32_t a) {
    asm volatile("ldmatrix.sync.aligned.m8n8.x4.shared.b16 {%0,%1,%2,%3}, [%4];"
                 : "=r"(r[0]), "=r"(r[1]), "=r"(r[2]), "=r"(r[3]) : "r"(a));
}
__device__ __forceinline__ void mma16816(float* d, const uint32_t* a,
                                         uint32_t b0, uint32_t b1) {
    asm volatile(
        "mma.sync.aligned.m16n8k16.row.col.f32.bf16.bf16.f32 "
        "{%0,%1,%2,%3}, {%4,%5,%6,%7}, {%8,%9}, {%0,%1,%2,%3};"
        : "+f"(d[0]), "+f"(d[1]), "+f"(d[2]), "+f"(d[3])
        : "r"(a[0]), "r"(a[1]), "r"(a[2]), "r"(a[3]), "r"(b0), "r"(b1));
}
__device__ __forceinline__ void cpasync16(uint32_t dst, const void* src) {
    asm volatile("cp.async.cg.shared.global [%0], [%1], 16;"
                 :: "r"(dst), "l"(src) : "memory");
}
__device__ __forceinline__ void split_bf(float v, unsigned short& h, unsigned short& l) {
    __nv_bfloat16 hb = __float2bfloat16_rn(v);
    float r = v - __bfloat162float(hb);
    __nv_bfloat16 lb = __float2bfloat16_rn(r);
    h = __bfloat16_as_ushort(hb);
    l = __bfloat16_as_ushort(lb);
}

// ---------------------------------------------------------------------------
// K1a: partial lhs_t over 128-node groups (coalesced)     grid(8,16) x 256
// ---------------------------------------------------------------------------
__global__ void __launch_bounds__(256) k_lhs_p(const float* __restrict__ x,
                                               const float* __restrict__ U1) {
    int nb = blockIdx.x, b = blockIdx.y;
    int tid = threadIdx.x, w = tid >> 5, lane = tid & 31;
    float acc[24];
    #pragma unroll
    for (int j = 0; j < 24; j++) acc[j] = 0.f;
    for (int i = 0; i < 16; i++) {
        int n = nb * 128 + w * 16 + i;
        float u = U1[n];
        const float* row = x + ((size_t)(b * NN + n)) * FT;
        #pragma unroll
        for (int j = 0; j < 24; j++) acc[j] += u * row[lane + 32 * j];
    }
    __shared__ float sp[8][FT];
    #pragma unroll
    for (int j = 0; j < 24; j++) sp[w][lane + 32 * j] = acc[j];
    __syncthreads();
    for (int ft = tid; ft < FT; ft += 256) {
        float v = 0.f;
        #pragma unroll
        for (int ww = 0; ww < 8; ww++) v += sp[ww][ft];
        g_lpart[(b * 8 + nb) * FT + ft] = v;
    }
}
__global__ void __launch_bounds__(256) k_lhs_red() {
    int b = blockIdx.x, tid = threadIdx.x;
    for (int ft = tid; ft < FT; ft += 256) {
        float v = 0.f;
        #pragma unroll
        for (int nb = 0; nb < 8; nb++) v += g_lpart[(b * 8 + nb) * FT + ft];
        int f = ft / NT, t = ft - f * NT;
        g_lhs_t[(b * NT + t) * NF + f] = v;
    }
}

// ---------------------------------------------------------------------------
// K2: rhs_t[b,n,t] = sum_f U3[f] * x[b,n,f,t]             grid(32,16) x 256
// ---------------------------------------------------------------------------
__global__ void __launch_bounds__(256) k_rhs_t(const float* __restrict__ x,
                                               const float* __restrict__ U3) {
    int b = blockIdx.y, n0 = blockIdx.x * 32;
    int tid = threadIdx.x;
    const float* xb = x + (size_t)b * NN * FT;
    int e0 = tid, e1 = tid + 256, e2 = tid + 512;
    size_t b0 = (size_t)(n0 + e0 / 24) * FT + (e0 % 24);
    size_t b1 = (size_t)(n0 + e1 / 24) * FT + (e1 % 24);
    size_t b2 = (size_t)(n0 + e2 / 24) * FT + (e2 % 24);
    float a0 = 0.f, a1 = 0.f, a2 = 0.f;
    #pragma unroll
    for (int f = 0; f < NF; f++) {
        float u = U3[f];
        int off = f * NT;
        a0 += u * xb[b0 + off];
        a1 += u * xb[b1 + off];
        a2 += u * xb[b2 + off];
    }
    float* o = g_rhs_t + (size_t)b * NN * NT + (size_t)n0 * NT;
    o[e0] = a0; o[e1] = a1; o[e2] = a2;
}

// ---------------------------------------------------------------------------
// K3: E_pre[b,t,s]                                        grid(24,16) x 256
// ---------------------------------------------------------------------------
__global__ void __launch_bounds__(256) k_epre(const float* __restrict__ U2) {
    int t = blockIdx.x, b = blockIdx.y;
    __shared__ float lt[NF];
    __shared__ float red[8][NT];
    int tid = threadIdx.x;
    if (tid < NF) lt[tid] = g_lhs_t[(b * NT + t) * NF + tid];
    __syncthreads();
    float pe[NT];
    #pragma unroll
    for (int s = 0; s < NT; s++) pe[s] = 0.f;
    for (int n = tid; n < NN; n += 256) {
        float l2 = 0.f;
        #pragma unroll
        for (int f = 0; f < NF; f++) l2 += lt[f] * U2[f * NN + n];
        const float* rr = &g_rhs_t[((size_t)b * NN + n) * NT];
        #pragma unroll
        for (int s = 0; s < NT; s++) pe[s] += l2 * rr[s];
    }
    int lane = tid & 31, w = tid >> 5;
    #pragma unroll
    for (int s = 0; s < NT; s++) {
        float v = pe[s];
        #pragma unroll
        for (int o = 16; o; o >>= 1) v += __shfl_xor_sync(0xffffffffu, v, o);
        if (lane == 0) red[w][s] = v;
    }
    __syncthreads();
    if (tid < NT) {
        float v = 0.f;
        #pragma unroll
        for (int w2 = 0; w2 < 8; w2++) v += red[w2][tid];
        g_Epre[b * NT * NT + t * NT + tid] = v;
    }
}

// ---------------------------------------------------------------------------
// K4: E = softmax(E_pre, axis=t)                          grid(24,16) x 32
// ---------------------------------------------------------------------------
__global__ void k_esm() {
    int s = blockIdx.x, b = blockIdx.y, lane = threadIdx.x;
    float v = (lane < NT) ? g_Epre[b * NT * NT + lane * NT + s] : -3.4e38f;
    float mx = v;
    #pragma unroll
    for (int o = 16; o; o >>= 1) mx = fmaxf(mx, __shfl_xor_sync(0xffffffffu, mx, o));
    float e = (lane < NT) ? __expf(v - mx) : 0.f;
    float sm = e;
    #pragma unroll
    for (int o = 16; o; o >>= 1) sm += __shfl_xor_sync(0xffffffffu, sm, o);
    if (lane < NT) g_E[b * NT * NT + lane * NT + s] = e / sm;
}

// ---------------------------------------------------------------------------
// K5: x_TAt[b,n,f,s] = sum_t x[b,n,f,t]*E[b,t,s]          grid(2048) x 256
// ---------------------------------------------------------------------------
__global__ void __launch_bounds__(256) k_xtat(const float* __restrict__ x) {
    int b = blockIdx.x >> 7;
    size_t row = (size_t)blockIdx.x * 256 + threadIdx.x;
    __shared__ float Es[NT * NT];
    for (int i = threadIdx.x; i < NT * NT; i += 256) Es[i] = g_E[b * NT * NT + i];
    __syncthreads();
    float in[NT];
    const float4* ip = (const float4*)(x + row * NT);
    #pragma unroll
    for (int i = 0; i < 6; i++) ((float4*)in)[i] = ip[i];
    float o[NT];
    #pragma unroll
    for (int s = 0; s < NT; s++) {
        float a = 0.f;
        #pragma unroll
        for (int t = 0; t < NT; t++) a += in[t] * Es[t * NT + s];
        o[s] = a;
    }
    float4* op = (float4*)(g_xTAt + row * NT);
    #pragma unroll
    for (int i = 0; i < 6; i++) op[i] = ((float4*)o)[i];
}

// ---------------------------------------------------------------------------
// K6: lhs2s[b,n,t]                                        grid(2048) x 256
// ---------------------------------------------------------------------------
__global__ void __launch_bounds__(256) k_lhs2s(const float* __restrict__ W1,
                                               const float* __restrict__ W2) {
    int bb = blockIdx.x;
    int b = bb >> 7;
    int n0 = (bb & 127) * 8;
    __shared__ float ls[8][NF];
    int tid = threadIdx.x;
    int ni = tid >> 5, f = tid & 31;
    const float* r = g_xTAt + ((size_t)(b * NN + n0 + ni) * NF + f) * NT;
    float s = 0.f;
    #pragma unroll
    for (int t = 0; t < NT; t++) s += r[t] * W1[t];
    ls[ni][f] = s;
    __syncthreads();
    if (tid < 8 * NT) {
        int ni2 = tid / NT, t = tid - ni2 * NT;
        float v = 0.f;
        #pragma unroll
        for (int ff = 0; ff < NF; ff++) v += ls[ni2][ff] * W2[ff * NT + t];
        g_lhs2s[((size_t)b * NN + n0 + ni2) * NT + t] = v;
    }
}

// ---------------------------------------------------------------------------
// K7: rhs_s[b,t,m] = sum_f W3[f] * xTAt[b,m,f,t]          grid(32,16) x 256
// ---------------------------------------------------------------------------
__global__ void __launch_bounds__(256) k_rhs_s(const float* __restrict__ W3) {
    int b = blockIdx.y, m0 = blockIdx.x * 32;
    int tid = threadIdx.x;
    const float* xb = g_xTAt + (size_t)b * NN * FT;
    int e0 = tid, e1 = tid + 256, e2 = tid + 512;
    int m_0 = e0 / 24, t_0 = e0 - m_0 * 24;
    int m_1 = e1 / 24, t_1 = e1 - m_1 * 24;
    int m_2 = e2 / 24, t_2 = e2 - m_2 * 24;
    size_t b0 = (size_t)(m0 + m_0) * FT + t_0;
    size_t b1 = (size_t)(m0 + m_1) * FT + t_1;
    size_t b2 = (size_t)(m0 + m_2) * FT + t_2;
    float a0 = 0.f, a1 = 0.f, a2 = 0.f;
    #pragma unroll
    for (int f = 0; f < NF; f++) {
        float u = W3[f];
        int off = f * NT;
        a0 += u * xb[b0 + off];
        a1 += u * xb[b1 + off];
        a2 += u * xb[b2 + off];
    }
    float* o = g_rhs_s + (size_t)b * NT * NN;
    o[t_0 * NN + m0 + m_0] = a0;
    o[t_1 * NN + m0 + m_1] = a1;
    o[t_2 * NN + m0 + m_2] = a2;
}

// ---------------------------------------------------------------------------
// K8: S_pre[b,n,m] = sum_t lhs2s[b,n,t]*rhs_s[b,t,m]      grid(16,16,16) x 256
// ---------------------------------------------------------------------------
__global__ void __launch_bounds__(256) k_spre() {
    int b = blockIdx.z;
    int mtile = blockIdx.x * 64;
    int ntile = blockIdx.y * 64;
    __shared__ __align__(16) float Ls[64 * 25];
    __shared__ __align__(16) float Rs[24 * 64];
    int tid = threadIdx.x;
    const float* L = g_lhs2s + (size_t)b * NN * NT;
    const float* R = g_rhs_s + (size_t)b * NT * NN;
    #pragma unroll
    for (int i = 0; i < 6; i++) {
        int e = tid + i * 256;
        int nn = e / 24, tt = e - nn * 24;
        Ls[nn * 25 + tt] = L[(size_t)(ntile + nn) * NT + tt];
        int t2 = e >> 6, m2 = e & 63;
        Rs[e] = R[(size_t)t2 * NN + mtile + m2];
    }
    __syncthreads();
    int tx = tid & 15, ty = tid >> 4;
    float acc[4][4];
    #pragma unroll
    for (int i = 0; i < 4; i++)
        #pragma unroll
        for (int j = 0; j < 4; j++) acc[i][j] = 0.f;
    #pragma unroll
    for (int kk = 0; kk < NT; kk++) {
        float a[4], bb[4];
        #pragma unroll
        for (int i = 0; i < 4; i++) a[i] = Ls[(ty * 4 + i) * 25 + kk];
        float4 rv = *(const float4*)&Rs[kk * 64 + tx * 4];
        bb[0] = rv.x; bb[1] = rv.y; bb[2] = rv.z; bb[3] = rv.w;
        #pragma unroll
        for (int i = 0; i < 4; i++)
            #pragma unroll
            for (int j = 0; j < 4; j++) acc[i][j] += a[i] * bb[j];
    }
    float* S = g_Spre + (size_t)b * NN * NN;
    #pragma unroll
    for (int i = 0; i < 4; i++) {
        float4 o;
        o.x = acc[i][0]; o.y = acc[i][1]; o.z = acc[i][2]; o.w = acc[i][3];
        *(float4*)&S[(size_t)(ntile + ty * 4 + i) * NN + mtile + tx * 4] = o;
    }
}

// ---------------------------------------------------------------------------
// K9: colmax over n of S_pre                              grid(32,16) x 256
// ---------------------------------------------------------------------------
__global__ void __launch_bounds__(256) k_cmax() {
    int b = blockIdx.y, m0 = blockIdx.x * 32;
    int tid = threadIdx.x, w = tid >> 5, lane = tid & 31;
    const float* S = g_Spre + (size_t)b * NN * NN;
    float mx = -3.4e38f;
    for (int n = w; n < NN; n += 8)
        mx = fmaxf(mx, S[(size_t)n * NN + m0 + lane]);
    __shared__ float red[8][32];
    red[w][lane] = mx;
    __syncthreads();
    if (w == 0) {
        float v = red[0][lane];
        #pragma unroll
        for (int i = 1; i < 8; i++) v = fmaxf(v, red[i][lane]);
        g_cmax[b * NN + m0 + lane] = v;
    }
}

// ---------------------------------------------------------------------------
// K10: Sexp = exp(S_pre - colmax), icsum = 1/colsum       grid(32,16) x 256
// ---------------------------------------------------------------------------
__global__ void __launch_bounds__(256) k_sexp() {
    int b = blockIdx.y, m0 = blockIdx.x * 32;
    int tid = threadIdx.x, w = tid >> 5, lane = tid & 31;
    const float* S = g_Spre + (size_t)b * NN * NN;
    float* E = g_Sexp + (size_t)b * NN * NN;
    float mx = g_cmax[b * NN + m0 + lane];
    float s = 0.f;
    for (int n = w; n < NN; n += 8) {
        size_t i = (size_t)n * NN + m0 + lane;
        float v = __expf(S[i] - mx);
        E[i] = v;
        s += v;
    }
    __shared__ float red[8][32];
    red[w][lane] = s;
    __syncthreads();
    if (w == 0) {
        float v = red[0][lane];
        #pragma unroll
        for (int i = 1; i < 8; i++) v += red[i][lane];
        g_icsum[b * NN + m0 + lane] = 1.0f / v;
    }
}

// ---------------------------------------------------------------------------
// K11a: AT[kb][m][n] = bf16split( cheb[k][n][m]*Sexp[b][n][m]*icsum[b][m] )
// ---------------------------------------------------------------------------
__global__ void __launch_bounds__(256) k_mkA(const float* __restrict__ cheb) {
    int kb = blockIdx.z;
    int b = kb / 3, kk = kb - b * 3;
    int mtile = blockIdx.y * 64;
    int ntile = blockIdx.x * 64;
    __shared__ float tile[64][65];
    __shared__ float ics[64];
    int tid = threadIdx.x;
    const float* Sx = g_Sexp + (size_t)b * NN * NN;
    const float* Cb = cheb + (size_t)kk * NN * NN;
    if (tid < 64) ics[tid] = g_icsum[b * NN + mtile + tid];
    #pragma unroll
    for (int i = 0; i < 4; i++) {
        int idx = tid + i * 256;
        int n_loc = idx >> 4, m_loc = (idx & 15) * 4;
        size_t g = (size_t)(ntile + n_loc) * NN + mtile + m_loc;
        float4 sv = *(const float4*)&Sx[g];
        float4 cv = *(const float4*)&Cb[g];
        tile[m_loc + 0][n_loc] = sv.x * cv.x;
        tile[m_loc + 1][n_loc] = sv.y * cv.y;
        tile[m_loc + 2][n_loc] = sv.z * cv.z;
        tile[m_loc + 3][n_loc] = sv.w * cv.w;
    }
    __syncthreads();
    int m_loc = tid >> 2, q = tid & 3;
    float icm = ics[m_loc];
    unsigned short uh[16], ul[16];
    #pragma unroll
    for (int u = 0; u < 16; u++)
        split_bf(tile[m_loc][q * 16 + u] * icm, uh[u], ul[u]);
    uint32_t wh[8], wl[8];
    #pragma unroll
    for (int p = 0; p < 8; p++) {
        wh[p] = (uint32_t)uh[2 * p] | ((uint32_t)uh[2 * p + 1] << 16);
        wl[p] = (uint32_t)ul[2 * p] | ((uint32_t)ul[2 * p + 1] << 16);
    }
    size_t off = ((size_t)kb * NN + mtile + m_loc) * NN + ntile + q * 16;
    uint4* dh = (uint4*)(g_AT_hi + off);
    uint4* dl = (uint4*)(g_AT_lo + off);
    dh[0] = make_uint4(wh[0], wh[1], wh[2], wh[3]);
    dh[1] = make_uint4(wh[4], wh[5], wh[6], wh[7]);
    dl[0] = make_uint4(wl[0], wl[1], wl[2], wl[3]);
    dl[1] = make_uint4(wl[4], wl[5], wl[6], wl[7]);
}

// ---------------------------------------------------------------------------
// K11b: XT[b][j][n] = bf16split( x[b][n][j] )             grid(16,12,16) x 256
// ---------------------------------------------------------------------------
__global__ void __launch_bounds__(256) k_mkX(const float* __restrict__ x) {
    int b = blockIdx.z;
    int jtile = blockIdx.y * 64;
    int ntile = blockIdx.x * 64;
    __shared__ float tile[64][65];
    int tid = threadIdx.x;
    #pragma unroll
    for (int i = 0; i < 4; i++) {
        int idx = tid + i * 256;
        int n_loc = idx >> 4, j_loc = (idx & 15) * 4;
        size_t g = (size_t)(b * NN + ntile + n_loc) * FT + jtile + j_loc;
        float4 v = *(const float4*)&x[g];
        tile[j_loc + 0][n_loc] = v.x;
        tile[j_loc + 1][n_loc] = v.y;
        tile[j_loc + 2][n_loc] = v.z;
        tile[j_loc + 3][n_loc] = v.w;
    }
    __syncthreads();
    int j_loc = tid >> 2, q = tid & 3;
    unsigned short uh[16], ul[16];
    #pragma unroll
    for (int u = 0; u < 16; u++)
        split_bf(tile[j_loc][q * 16 + u], uh[u], ul[u]);
    uint32_t wh[8], wl[8];
    #pragma unroll
    for (int p = 0; p < 8; p++) {
        wh[p] = (uint32_t)uh[2 * p] | ((uint32_t)uh[2 * p + 1] << 16);
        wl[p] = (uint32_t)ul[2 * p] | ((uint32_t)ul[2 * p + 1] << 16);
    }
    size_t off = ((size_t)b * FT + jtile + j_loc) * NN + ntile + q * 16;
    uint4* dh = (uint4*)(g_XT_hi + off);
    uint4* dl = (uint4*)(g_XT_lo + off);
    dh[0] = make_uint4(wh[0], wh[1], wh[2], wh[3]);
    dh[1] = make_uint4(wh[4], wh[5], wh[6], wh[7]);
    dl[0] = make_uint4(wl[0], wl[1], wl[2], wl[3]);
    dl[1] = make_uint4(wl[4], wl[5], wl[6], wl[7]);
}

// ---------------------------------------------------------------------------
// K12 (dominant): mma.sync bf16 GEMM.  D[m,j] = sum_n AT[m,n]*XT[j,n],
//   3-term compensated (AhiXhi + AhiXlo + AloXhi).
//   CTA 128m x 128j, 8 warps (2m x 4j -> warp 64x32), KC=64, double buffer.
//   grid(6, 8, 48) x 256, smem 73728B
// ---------------------------------------------------------------------------
constexpr int KSTAGE_BYTES = 36864;   // A 128*144 + X 128*144
constexpr int MMA_SMEM = 2 * KSTAGE_BYTES;

__global__ void __launch_bounds__(256) k_mma2() {
    extern __shared__ __align__(16) unsigned char smb[];
    int tid = threadIdx.x, lane = tid & 31, wid = tid >> 5;
    int kb = blockIdx.z;
    int b = kb / 3, kk = kb - b * 3;
    int m0 = blockIdx.y * 128;
    int j0 = blockIdx.x * 128;
    const unsigned short* Ah = g_AT_hi + (size_t)kb * NN * NN;
    const unsigned short* Al = g_AT_lo + (size_t)kb * NN * NN;
    const unsigned short* Xh = g_XT_hi + (size_t)b * FT * NN;
    const unsigned short* Xl = g_XT_lo + (size_t)b * FT * NN;
    int warp_m = wid >> 2, warp_j = wid & 3;

    float d[4][4][4];
    #pragma unroll
    for (int i = 0; i < 4; i++)
        #pragma unroll
        for (int j = 0; j < 4; j++)
            #pragma unroll
            for (int q = 0; q < 4; q++) d[i][j][q] = 0.f;

    // lane addressing for ldmatrix
    int arow = (lane < 16) ? lane : (lane - 16);
    int ako  = (lane < 16) ? 0 : 8;
    int brow = (lane & 7) + ((lane >> 4) << 3);
    int bko  = (lane & 8) ? 8 : 0;

    auto issue = [&](int s) {
        int term = s >> 4, kc = s & 15, n0 = kc * 64;
        const unsigned short* As = (term < 2) ? Ah : Al;
        const unsigned short* Xs = (term == 1) ? Xl : Xh;
        unsigned char* buf = smb + (s & 1) * KSTAGE_BYTES;
        #pragma unroll
        for (int i = 0; i < 4; i++) {
            int idx = tid + i * 256;
            int r = idx >> 3, c = idx & 7;
            cpasync16(smem_u32(buf + r * 144 + c * 16),
                      As + (size_t)(m0 + r) * NN + n0 + c * 8);
            cpasync16(smem_u32(buf + 18432 + r * 144 + c * 16),
                      Xs + (size_t)(j0 + r) * NN + n0 + c * 8);
        }
        asm volatile("cp.async.commit_group;" ::: "memory");
    };

    issue(0);
    for (int s = 0; s < 48; s++) {
        if (s + 1 < 48) {
            issue(s + 1);
            asm volatile("cp.async.wait_group 1;" ::: "memory");
        } else {
            asm volatile("cp.async.wait_group 0;" ::: "memory");
        }
        __syncthreads();
        unsigned char* buf = smb + (s & 1) * KSTAGE_BYTES;
        uint32_t abase = smem_u32(buf);
        uint32_t xbase = smem_u32(buf + 18432);
        #pragma unroll
        for (int ks = 0; ks < 4; ks++) {
            uint32_t afr[4][4], bfr[2][4];
            #pragma unroll
            for (int mt = 0; mt < 4; mt++)
                ldmx4(afr[mt], abase + (warp_m * 64 + mt * 16 + arow) * 144 +
                               (ks * 16 + ako) * 2);
            #pragma unroll
            for (int jp = 0; jp < 2; jp++)
                ldmx4(bfr[jp], xbase + (warp_j * 32 + jp * 16 + brow) * 144 +
                               (ks * 16 + bko) * 2);
            #pragma unroll
            for (int mt = 0; mt < 4; mt++)
                #pragma unroll
                for (int jt = 0; jt < 4; jt++)
                    mma16816(d[mt][jt], afr[mt],
                             bfr[jt >> 1][2 * (jt & 1)],
                             bfr[jt >> 1][2 * (jt & 1) + 1]);
        }
        __syncthreads();
    }

    float* ob = g_rhs_all + (size_t)(kk * NB + b) * NN * FT;
    int mb = m0 + warp_m * 64, jb = j0 + warp_j * 32;
    #pragma unroll
    for (int mt = 0; mt < 4; mt++)
        #pragma unroll
        for (int jt = 0; jt < 4; jt++) {
            int row = mb + mt * 16 + (lane >> 2);
            int col = jb + jt * 8 + 2 * (lane & 3);
            float2 v0; v0.x = d[mt][jt][0]; v0.y = d[mt][jt][1];
            float2 v1; v1.x = d[mt][jt][2]; v1.y = d[mt][jt][3];
            *(float2*)&ob[(size_t)row * FT + col] = v0;
            *(float2*)&ob[(size_t)(row + 8) * FT + col] = v1;
        }
}

// ---------------------------------------------------------------------------
// K13: fused tail, register-blocked + f32x2.
//   grid(128,16) x 256, 210KB smem
// ---------------------------------------------------------------------------
constexpr int TAIL_SMEM_FLOATS = 6144 + 12288 + 2048 + 4 * 64 + 13312 + 18432;

__global__ void __launch_bounds__(256) k_tail(
    const float* __restrict__ x, const float* __restrict__ Theta,
    const float* __restrict__ tcw, const float* __restrict__ tcb,
    const float* __restrict__ rcw, const float* __restrict__ rcb,
    const float* __restrict__ gma, const float* __restrict__ bet,
    float* __restrict__ out) {
    extern __shared__ float smf[];
    float* Th = smf;               // [k][f][o]        6144
    float* Wt = Th + 6144;         // [cc][r][ct]      12288
    float* Wr = Wt + 12288;        // [f][ct]          2048
    float* Bc = Wr + 2048;
    float* Br = Bc + 64;
    float* Ga = Br + 64;
    float* Be = Ga + 64;
    float* SG = Be + 64;           // [m][cc][26]      13312
    float* BUF = SG + 13312;       // rhs 18432 -> x 6144 + z 12288

    int b = blockIdx.y, m0 = blockIdx.x * 8;
    int tid = threadIdx.x;
    for (int i = tid; i < 6144; i += 256) Th[i] = Theta[i];
    for (int i = tid; i < 12288; i += 256) {
        int cc = i / 192, rem = i - cc * 192;
        int r = rem >> 6, ct = rem & 63;
        Wt[i] = tcw[ct * 192 + cc * 3 + r];
    }
    for (int i = tid; i < 2048; i += 256) {
        int f = i >> 6, ct = i & 63;
        Wr[i] = rcw[ct * 32 + f];
    }
    if (tid < 64) { Bc[tid] = tcb[tid]; Br[tid] = rcb[tid]; Ga[tid] = gma[tid]; Be[tid] = bet[tid]; }
    for (int i = tid; i < 13312; i += 256) SG[i] = 0.f;
    for (int e = tid; e < 18432; e += 256) {
        int m = e / 2304, r = e - m * 2304;
        int k = r / 768, ft = r - k * 768;
        BUF[e] = g_rhs_all[((size_t)(k * NB + b) * NN + m0 + m) * FT + ft];
    }
    __syncthreads();

    // Phase 1: sg = relu(Theta contraction). 384 units (m x 6tg x 8og)
    for (int u = tid; u < 384; u += 256) {
        int m = u / 48, rr = u - m * 48;
        int tg = rr >> 3, og = rr & 7;
        int t0 = tg * 4, o0 = og * 8;
        unsigned long long acc[4][4];
        #pragma unroll
        for (int i = 0; i < 4; i++)
            #pragma unroll
            for (int p = 0; p < 4; p++) acc[i][p] = 0ull;
        #pragma unroll
        for (int k = 0; k < NK; k++) {
            const float* bb = &BUF[m * 2304 + k * 768];
            const float* tt = &Th[k * 2048];
            #pragma unroll 4
            for (int f = 0; f < NF; f++) {
                float4 bk = *(const float4*)&bb[f * 24 + t0];
                const unsigned long long* tp =
                    (const unsigned long long*)&tt[f * 64 + o0];
                unsigned long long bp0 = pack2(bk.x), bp1 = pack2(bk.y);
                unsigned long long bp2 = pack2(bk.z), bp3 = pack2(bk.w);
                #pragma unroll
                for (int p = 0; p < 4; p++) {
                    unsigned long long tv = tp[p];
                    ffma2(acc[0][p], bp0, tv);
                    ffma2(acc[1][p], bp1, tv);
                    ffma2(acc[2][p], bp2, tv);
                    ffma2(acc[3][p], bp3, tv);
                }
            }
        }
        #pragma unroll
        for (int p = 0; p < 4; p++) {
            int o = o0 + 2 * p;
            #pragma unroll
            for (int i = 0; i < 4; i++) {
                SG[(m * 64 + o) * 26 + t0 + i + 1] = fmaxf(lo32(acc[i][p]), 0.f);
                SG[(m * 64 + o + 1) * 26 + t0 + i + 1] = fmaxf(hi32(acc[i][p]), 0.f);
            }
        }
    }
    __syncthreads();

    // stage x rows
    for (int e = tid; e < 6144; e += 256) {
        int m = e / 768, ft = e - m * 768;
        BUF[e] = x[((size_t)(b * NN + m0 + m)) * FT + ft];
    }
    __syncthreads();

    // Phase 2: z = relu(timeconv + residual). 256 units (m x 4tg(6t) x 8cg)
    {
        int u = tid;
        int m = u >> 5, rr = u & 31;
        int tg = rr >> 3, cg = rr & 7;
        int t0 = tg * 6, c0 = cg * 8;
        unsigned long long z[6][4];
        #pragma unroll
        for (int i = 0; i < 6; i++)
            #pragma unroll
            for (int p = 0; p < 4; p++) z[i][p] = 0ull;
        const float* sgm = &SG[m * 1664];
        for (int cc = 0; cc < NCC; cc++) {
            const float* srow = &sgm[cc * 26 + t0];
            unsigned long long sp[8];
            #pragma unroll
            for (int j = 0; j < 8; j++) sp[j] = pack2(srow[j]);
            const float* w = &Wt[cc * 192 + c0];
            #pragma unroll
            for (int r = 0; r < 3; r++) {
                const unsigned long long* wp = (const unsigned long long*)&w[r * 64];
                #pragma unroll
                for (int p = 0; p < 4; p++) {
                    unsigned long long wv = wp[p];
                    #pragma unroll
                    for (int i = 0; i < 6; i++) ffma2(z[i][p], sp[i + r], wv);
                }
            }
        }
        const float* xm = &BUF[m * 768];
        #pragma unroll 4
        for (int f = 0; f < NF; f++) {
            const float* xr = &xm[f * 24 + t0];
            float2 x01 = *(const float2*)&xr[0];
            float2 x23 = *(const float2*)&xr[2];
            float2 x45 = *(const float2*)&xr[4];
            unsigned long long xp[6] = {pack2(x01.x), pack2(x01.y), pack2(x23.x),
                                        pack2(x23.y), pack2(x45.x), pack2(x45.y)};
            const unsigned long long* wp = (const unsigned long long*)&Wr[f * 64 + c0];
            #pragma unroll
            for (int p = 0; p < 4; p++) {
                unsigned long long wv = wp[p];
                #pragma unroll
                for (int i = 0; i < 6; i++) ffma2(z[i][p], xp[i], wv);
            }
        }
        float* zb = &BUF[6144 + m * 1536];
        #pragma unroll
        for (int p = 0; p < 4; p++) {
            int c = c0 + 2 * p;
            float b0 = Bc[c] + Br[c], b1 = Bc[c + 1] + Br[c + 1];
            #pragma unroll
            for (int i = 0; i < 6; i++) {
                zb[c * 24 + t0 + i] = fmaxf(lo32(z[i][p]) + b0, 0.f);
                zb[(c + 1) * 24 + t0 + i] = fmaxf(hi32(z[i][p]) + b1, 0.f);
            }
        }
    }
    __syncthreads();

    // Phase 3: LayerNorm over ct, write out[b,m,ct,t]
    for (int p = tid; p < 8 * NT; p += 256) {
        int m = p / NT, t = p - m * NT;
        const float* zz = &BUF[6144 + m * 1536 + t];
        float mu = 0.f;
        #pragma unroll
        for (int c = 0; c < NCT; c++) mu += zz[c * NT];
        mu *= (1.f / 64.f);
        float var = 0.f;
        #pragma unroll
        for (int c = 0; c < NCT; c++) { float dd = zz[c * NT] - mu; var += dd * dd; }
        var *= (1.f / 64.f);
        float rs = rsqrtf(var + 1e-5f);
        float* op = out + ((size_t)(b * NN + m0 + m) * NCT) * NT + t;
        #pragma unroll
        for (int c = 0; c < NCT; c++)
            op[c * NT] = (zz[c * NT] - mu) * rs * Ga[c] + Be[c];
    }
}

// ---------------------------------------------------------------------------
extern "C" void kernel_launch(void* const* d_in, const int* in_sizes, int n_in,
                              void* d_out, int out_size) {
    const float* x     = (const float*)d_in[0];
    const float* W1    = (const float*)d_in[1];
    const float* W2    = (const float*)d_in[2];
    const float* W3    = (const float*)d_in[3];
    const float* U1    = (const float*)d_in[4];
    const float* U2    = (const float*)d_in[5];
    const float* U3    = (const float*)d_in[6];
    const float* cheb  = (const float*)d_in[7];
    const float* Theta = (const float*)d_in[8];
    const float* tc_w  = (const float*)d_in[9];
    const float* tc_b  = (const float*)d_in[10];
    const float* rc_w  = (const float*)d_in[11];
    const float* rc_b  = (const float*)d_in[12];
    const float* gamma = (const float*)d_in[13];
    const float* beta  = (const float*)d_in[14];
    float* out = (float*)d_out;

    cudaFuncSetAttribute(k_tail, cudaFuncAttributeMaxDynamicSharedMemorySize,
                         TAIL_SMEM_FLOATS * 4);
    cudaFuncSetAttribute(k_mma2, cudaFuncAttributeMaxDynamicSharedMemorySize,
                         MMA_SMEM);

    // temporal attention
    k_lhs_p<<<dim3(8, NB), 256>>>(x, U1);
    k_lhs_red<<<NB, 256>>>();
    k_rhs_t<<<dim3(NN / 32, NB), 256>>>(x, U3);
    k_epre<<<dim3(NT, NB), 256>>>(U2);
    k_esm<<<dim3(NT, NB), 32>>>();
    k_xtat<<<NB * 128, 256>>>(x);
    // spatial attention
    k_lhs2s<<<NB * 128, 256>>>(W1, W2);
    k_rhs_s<<<dim3(NN / 32, NB), 256>>>(W3);
    k_spre<<<dim3(16, 16, NB), 256>>>();
    k_cmax<<<dim3(NN / 32, NB), 256>>>();
    k_sexp<<<dim3(NN / 32, NB), 256>>>();
    // operand prep for tensor-core GEMM
    k_mkA<<<dim3(16, 16, NB * NK), 256>>>(cheb);
    k_mkX<<<dim3(16, 12, NB), 256>>>(x);
    // chebyshev graph conv on mma.sync
    k_mma2<<<dim3(6, 8, NB * NK), 256, MMA_SMEM>>>();
    // fused Theta + timeconv + residual + LN
    k_tail<<<dim3(NN / 8, NB), 256, TAIL_SMEM_FLOATS * 4>>>(
        x, Theta, tc_w, tc_b, rc_w, rc_b, gamma, beta, out);
}

// round 15
// speedup vs baseline: 2.5268x; 1.1478x over previous
#include <cuda_runtime.h>
#include <cuda_bf16.h>
#include <cstdint>
#include <cstddef>

// ---------------------------------------------------------------------------
// ASTGCN block. B=16, N=1024, F=32, T=24, K=3, CC=CT=64.
// ---------------------------------------------------------------------------

constexpr int NB  = 16;
constexpr int NN  = 1024;
constexpr int NF  = 32;
constexpr int NT  = 24;
constexpr int NK  = 3;
constexpr int NCC = 64;
constexpr int NCT = 64;
constexpr int FT  = NF * NT;   // 768

// ------------------------- scratch (device globals) ------------------------
__device__ float g_lpart[NB * 8 * FT];
__device__ float g_lhs_t[NB * NT * NF];
__device__ float g_rhs_t[NB * NN * NT];
__device__ float g_Epre[NB * NT * NT];
__device__ float g_E[NB * NT * NT];
__device__ float g_ew1[NB * NT];
__device__ float g_xw3[NB * NN * NT];
__device__ float g_lhs2s[NB * NN * NT];
__device__ float g_rhs_s[NB * NT * NN];
__device__ float g_Spre[(size_t)NB * NN * NN];
__device__ float g_cmax[NB * NN];
__device__ float g_Sexp[(size_t)NB * NN * NN];
__device__ float g_icsum[NB * NN];
__device__ __align__(16) unsigned short g_AT_hi[(size_t)NK * NB * NN * NN]; // [b*3+k][m][n]
__device__ __align__(16) unsigned short g_AT_lo[(size_t)NK * NB * NN * NN];
__device__ __align__(16) unsigned short g_XT_hi[(size_t)NB * FT * NN];      // [b][j][n]
__device__ __align__(16) unsigned short g_XT_lo[(size_t)NB * FT * NN];
__device__ __align__(16) float g_rhs_all[(size_t)NK * NB * NN * FT];  // [(k*NB+b)][m][ft]
__device__ __align__(16) float g_Wt[12288];   // [cc][r][ct]
__device__ __align__(16) float g_Wr[2048];    // [f][ct]

// ------------------------------ helpers ------------------------------------
__device__ __forceinline__ uint32_t smem_u32(const void* p) {
    uint32_t a;
    asm("{ .reg .u64 t; cvta.to.shared.u64 t, %1; cvt.u32.u64 %0, t; }"
        : "=r"(a) : "l"(p));
    return a;
}
__device__ __forceinline__ void ffma2(unsigned long long& d,
                                      unsigned long long a,
                                      unsigned long long b) {
    asm("fma.rn.f32x2 %0, %1, %2, %0;" : "+l"(d) : "l"(a), "l"(b));
}
__device__ __forceinline__ unsigned long long pack2(float x) {
    unsigned long long r;
    asm("mov.b64 %0, {%1, %1};" : "=l"(r) : "f"(x));
    return r;
}
__device__ __forceinline__ float lo32(unsigned long long v) {
    return __uint_as_float((unsigned)(v & 0xffffffffull));
}
__device__ __forceinline__ float hi32(unsigned long long v) {
    return __uint_as_float((unsigned)(v >> 32));
}
__device__ __forceinline__ void ldmx4(uint32_t* r, uint32_t a) {
    asm volatile("ldmatrix.sync.aligned.m8n8.x4.shared.b16 {%0,%1,%2,%3}, [%4];"
                 : "=r"(r[0]), "=r"(r[1]), "=r"(r[2]), "=r"(r[3]) : "r"(a));
}
__device__ __forceinline__ void mma16816(float* d, const uint32_t* a,
                                         uint32_t b0, uint32_t b1) {
    asm volatile(
        "mma.sync.aligned.m16n8k16.row.col.f32.bf16.bf16.f32 "
        "{%0,%1,%2,%3}, {%4,%5,%6,%7}, {%8,%9}, {%0,%1,%2,%3};"
        : "+f"(d[0]), "+f"(d[1]), "+f"(d[2]), "+f"(d[3])
        : "r"(a[0]), "r"(a[1]), "r"(a[2]), "r"(a[3]), "r"(b0), "r"(b1));
}
__device__ __forceinline__ void cpasync16(uint32_t dst, const void* src) {
    asm volatile("cp.async.cg.shared.global [%0], [%1], 16;"
                 :: "r"(dst), "l"(src) : "memory");
}
__device__ __forceinline__ void split_bf(float v, unsigned short& h, unsigned short& l) {
    __nv_bfloat16 hb = __float2bfloat16_rn(v);
    float r = v - __bfloat162float(hb);
    __nv_bfloat16 lb = __float2bfloat16_rn(r);
    h = __bfloat16_as_ushort(hb);
    l = __bfloat16_as_ushort(lb);
}

// ---------------------------------------------------------------------------
// K0: transpose conv weights for the tail                 <<<1,256>>>
// ---------------------------------------------------------------------------
__global__ void __launch_bounds__(256) k_prep_w(const float* __restrict__ tcw,
                                                const float* __restrict__ rcw) {
    int tid = threadIdx.x;
    for (int i = tid; i < 12288; i += 256) {
        int cc = i / 192, rem = i - cc * 192;
        int r = rem >> 6, ct = rem & 63;
        g_Wt[i] = tcw[ct * 192 + cc * 3 + r];
    }
    for (int i = tid; i < 2048; i += 256) {
        int f = i >> 6, ct = i & 63;
        g_Wr[i] = rcw[ct * 32 + f];
    }
}

// ---------------------------------------------------------------------------
// K1a/K1b: lhs_t (coalesced partial reduce)
// ---------------------------------------------------------------------------
__global__ void __launch_bounds__(256) k_lhs_p(const float* __restrict__ x,
                                               const float* __restrict__ U1) {
    int nb = blockIdx.x, b = blockIdx.y;
    int tid = threadIdx.x, w = tid >> 5, lane = tid & 31;
    float acc[24];
    #pragma unroll
    for (int j = 0; j < 24; j++) acc[j] = 0.f;
    for (int i = 0; i < 16; i++) {
        int n = nb * 128 + w * 16 + i;
        float u = U1[n];
        const float* row = x + ((size_t)(b * NN + n)) * FT;
        #pragma unroll
        for (int j = 0; j < 24; j++) acc[j] += u * row[lane + 32 * j];
    }
    __shared__ float sp[8][FT];
    #pragma unroll
    for (int j = 0; j < 24; j++) sp[w][lane + 32 * j] = acc[j];
    __syncthreads();
    for (int ft = tid; ft < FT; ft += 256) {
        float v = 0.f;
        #pragma unroll
        for (int ww = 0; ww < 8; ww++) v += sp[ww][ft];
        g_lpart[(b * 8 + nb) * FT + ft] = v;
    }
}
__global__ void __launch_bounds__(256) k_lhs_red() {
    int b = blockIdx.x, tid = threadIdx.x;
    for (int ft = tid; ft < FT; ft += 256) {
        float v = 0.f;
        #pragma unroll
        for (int nb = 0; nb < 8; nb++) v += g_lpart[(b * 8 + nb) * FT + ft];
        int f = ft / NT, t = ft - f * NT;
        g_lhs_t[(b * NT + t) * NF + f] = v;
    }
}

// ---------------------------------------------------------------------------
// K2: rhs_t[b,n,t] = sum_f U3[f] * x[b,n,f,t]
// ---------------------------------------------------------------------------
__global__ void __launch_bounds__(256) k_rhs_t(const float* __restrict__ x,
                                               const float* __restrict__ U3) {
    int b = blockIdx.y, n0 = blockIdx.x * 32;
    int tid = threadIdx.x;
    const float* xb = x + (size_t)b * NN * FT;
    int e0 = tid, e1 = tid + 256, e2 = tid + 512;
    size_t b0 = (size_t)(n0 + e0 / 24) * FT + (e0 % 24);
    size_t b1 = (size_t)(n0 + e1 / 24) * FT + (e1 % 24);
    size_t b2 = (size_t)(n0 + e2 / 24) * FT + (e2 % 24);
    float a0 = 0.f, a1 = 0.f, a2 = 0.f;
    #pragma unroll
    for (int f = 0; f < NF; f++) {
        float u = U3[f];
        int off = f * NT;
        a0 += u * xb[b0 + off];
        a1 += u * xb[b1 + off];
        a2 += u * xb[b2 + off];
    }
    float* o = g_rhs_t + (size_t)b * NN * NT + (size_t)n0 * NT;
    o[e0] = a0; o[e1] = a1; o[e2] = a2;
}

// ---------------------------------------------------------------------------
// K3: E_pre
// ---------------------------------------------------------------------------
__global__ void __launch_bounds__(256) k_epre(const float* __restrict__ U2) {
    int t = blockIdx.x, b = blockIdx.y;
    __shared__ float lt[NF];
    __shared__ float red[8][NT];
    int tid = threadIdx.x;
    if (tid < NF) lt[tid] = g_lhs_t[(b * NT + t) * NF + tid];
    __syncthreads();
    float pe[NT];
    #pragma unroll
    for (int s = 0; s < NT; s++) pe[s] = 0.f;
    for (int n = tid; n < NN; n += 256) {
        float l2 = 0.f;
        #pragma unroll
        for (int f = 0; f < NF; f++) l2 += lt[f] * U2[f * NN + n];
        const float* rr = &g_rhs_t[((size_t)b * NN + n) * NT];
        #pragma unroll
        for (int s = 0; s < NT; s++) pe[s] += l2 * rr[s];
    }
    int lane = tid & 31, w = tid >> 5;
    #pragma unroll
    for (int s = 0; s < NT; s++) {
        float v = pe[s];
        #pragma unroll
        for (int o = 16; o; o >>= 1) v += __shfl_xor_sync(0xffffffffu, v, o);
        if (lane == 0) red[w][s] = v;
    }
    __syncthreads();
    if (tid < NT) {
        float v = 0.f;
        #pragma unroll
        for (int w2 = 0; w2 < 8; w2++) v += red[w2][tid];
        g_Epre[b * NT * NT + t * NT + tid] = v;
    }
}

// ---------------------------------------------------------------------------
// K4: E = softmax(E_pre, axis=t)
// ---------------------------------------------------------------------------
__global__ void k_esm() {
    int s = blockIdx.x, b = blockIdx.y, lane = threadIdx.x;
    float v = (lane < NT) ? g_Epre[b * NT * NT + lane * NT + s] : -3.4e38f;
    float mx = v;
    #pragma unroll
    for (int o = 16; o; o >>= 1) mx = fmaxf(mx, __shfl_xor_sync(0xffffffffu, mx, o));
    float e = (lane < NT) ? __expf(v - mx) : 0.f;
    float sm = e;
    #pragma unroll
    for (int o = 16; o; o >>= 1) sm += __shfl_xor_sync(0xffffffffu, sm, o);
    if (lane < NT) g_E[b * NT * NT + lane * NT + s] = e / sm;
}

// ---------------------------------------------------------------------------
// K4b: ew1[b,t] = sum_s E[b,t,s] * W1[s]                  <<<16,32>>>
// ---------------------------------------------------------------------------
__global__ void k_ew1(const float* __restrict__ W1) {
    int b = blockIdx.x, lane = threadIdx.x;
    if (lane < NT) {
        float s = 0.f;
        #pragma unroll
        for (int t = 0; t < NT; t++) s += g_E[b * 576 + lane * NT + t] * W1[t];
        g_ew1[b * NT + lane] = s;
    }
}

// ---------------------------------------------------------------------------
// K6: lhs2s[b,n,t'] = sum_f (sum_t x[b,n,f,t] ew1[b,t]) W2[f,t']
//   (x_TAt folded out)                                    grid(2048) x 256
// ---------------------------------------------------------------------------
__global__ void __launch_bounds__(256) k_lhs2(const float* __restrict__ x,
                                              const float* __restrict__ W2) {
    int bb = blockIdx.x;
    int b = bb >> 7;
    int n0 = (bb & 127) * 8;
    __shared__ float ls[8][NF];
    __shared__ float ew1s[NT];
    int tid = threadIdx.x;
    if (tid < NT) ew1s[tid] = g_ew1[b * NT + tid];
    __syncthreads();
    int ni = tid >> 5, f = tid & 31;
    const float* r = x + ((size_t)(b * NN + n0 + ni)) * FT + f * NT;
    float s = 0.f;
    #pragma unroll
    for (int t = 0; t < NT; t++) s += r[t] * ew1s[t];
    ls[ni][f] = s;
    __syncthreads();
    if (tid < 8 * NT) {
        int ni2 = tid / NT, t = tid - ni2 * NT;
        float v = 0.f;
        #pragma unroll
        for (int ff = 0; ff < NF; ff++) v += ls[ni2][ff] * W2[ff * NT + t];
        g_lhs2s[((size_t)b * NN + n0 + ni2) * NT + t] = v;
    }
}

// ---------------------------------------------------------------------------
// K7a: xw3[b,m,t] = sum_f W3[f] * x[b,m,f,t]              grid(32,16) x 256
// ---------------------------------------------------------------------------
__global__ void __launch_bounds__(256) k_xw3(const float* __restrict__ x,
                                             const float* __restrict__ W3) {
    int b = blockIdx.y, m0 = blockIdx.x * 32;
    int tid = threadIdx.x;
    const float* xb = x + (size_t)b * NN * FT;
    int e0 = tid, e1 = tid + 256, e2 = tid + 512;
    size_t b0 = (size_t)(m0 + e0 / 24) * FT + (e0 % 24);
    size_t b1 = (size_t)(m0 + e1 / 24) * FT + (e1 % 24);
    size_t b2 = (size_t)(m0 + e2 / 24) * FT + (e2 % 24);
    float a0 = 0.f, a1 = 0.f, a2 = 0.f;
    #pragma unroll
    for (int f = 0; f < NF; f++) {
        float u = W3[f];
        int off = f * NT;
        a0 += u * xb[b0 + off];
        a1 += u * xb[b1 + off];
        a2 += u * xb[b2 + off];
    }
    float* o = g_xw3 + (size_t)b * NN * NT + (size_t)m0 * NT;
    o[e0] = a0; o[e1] = a1; o[e2] = a2;
}

// ---------------------------------------------------------------------------
// K7b: rhs_s[b,t,m] = sum_s xw3[b,m,s] * E[b,s,t]         grid(32,16) x 256
// ---------------------------------------------------------------------------
__global__ void __launch_bounds__(256) k_rhs_s2() {
    int b = blockIdx.y, m0 = blockIdx.x * 32;
    int tid = threadIdx.x;
    __shared__ float xs[768];
    __shared__ float Es[576];
    for (int i = tid; i < 768; i += 256)
        xs[i] = g_xw3[(size_t)b * NN * NT + (size_t)m0 * NT + i];
    for (int i = tid; i < 576; i += 256) Es[i] = g_E[b * 576 + i];
    __syncthreads();
    #pragma unroll
    for (int i = 0; i < 3; i++) {
        int e = tid + i * 256;
        int m = e / 24, t = e - m * 24;
        float v = 0.f;
        #pragma unroll
        for (int s = 0; s < NT; s++) v += xs[m * 24 + s] * Es[s * 24 + t];
        g_rhs_s[(size_t)b * NT * NN + (size_t)t * NN + m0 + m] = v;
    }
}

// ---------------------------------------------------------------------------
// K8: S_pre GEMM
// ---------------------------------------------------------------------------
__global__ void __launch_bounds__(256) k_spre() {
    int b = blockIdx.z;
    int mtile = blockIdx.x * 64;
    int ntile = blockIdx.y * 64;
    __shared__ __align__(16) float Ls[64 * 25];
    __shared__ __align__(16) float Rs[24 * 64];
    int tid = threadIdx.x;
    const float* L = g_lhs2s + (size_t)b * NN * NT;
    const float* R = g_rhs_s + (size_t)b * NT * NN;
    #pragma unroll
    for (int i = 0; i < 6; i++) {
        int e = tid + i * 256;
        int nn = e / 24, tt = e - nn * 24;
        Ls[nn * 25 + tt] = L[(size_t)(ntile + nn) * NT + tt];
        int t2 = e >> 6, m2 = e & 63;
        Rs[e] = R[(size_t)t2 * NN + mtile + m2];
    }
    __syncthreads();
    int tx = tid & 15, ty = tid >> 4;
    float acc[4][4];
    #pragma unroll
    for (int i = 0; i < 4; i++)
        #pragma unroll
        for (int j = 0; j < 4; j++) acc[i][j] = 0.f;
    #pragma unroll
    for (int kk = 0; kk < NT; kk++) {
        float a[4], bb[4];
        #pragma unroll
        for (int i = 0; i < 4; i++) a[i] = Ls[(ty * 4 + i) * 25 + kk];
        float4 rv = *(const float4*)&Rs[kk * 64 + tx * 4];
        bb[0] = rv.x; bb[1] = rv.y; bb[2] = rv.z; bb[3] = rv.w;
        #pragma unroll
        for (int i = 0; i < 4; i++)
            #pragma unroll
            for (int j = 0; j < 4; j++) acc[i][j] += a[i] * bb[j];
    }
    float* S = g_Spre + (size_t)b * NN * NN;
    #pragma unroll
    for (int i = 0; i < 4; i++) {
        float4 o;
        o.x = acc[i][0]; o.y = acc[i][1]; o.z = acc[i][2]; o.w = acc[i][3];
        *(float4*)&S[(size_t)(ntile + ty * 4 + i) * NN + mtile + tx * 4] = o;
    }
}

// ---------------------------------------------------------------------------
// K9/K10: colmax, then Sexp + 1/colsum
// ---------------------------------------------------------------------------
__global__ void __launch_bounds__(256) k_cmax() {
    int b = blockIdx.y, m0 = blockIdx.x * 32;
    int tid = threadIdx.x, w = tid >> 5, lane = tid & 31;
    const float* S = g_Spre + (size_t)b * NN * NN;
    float mx = -3.4e38f;
    for (int n = w; n < NN; n += 8)
        mx = fmaxf(mx, S[(size_t)n * NN + m0 + lane]);
    __shared__ float red[8][32];
    red[w][lane] = mx;
    __syncthreads();
    if (w == 0) {
        float v = red[0][lane];
        #pragma unroll
        for (int i = 1; i < 8; i++) v = fmaxf(v, red[i][lane]);
        g_cmax[b * NN + m0 + lane] = v;
    }
}
__global__ void __launch_bounds__(256) k_sexp() {
    int b = blockIdx.y, m0 = blockIdx.x * 32;
    int tid = threadIdx.x, w = tid >> 5, lane = tid & 31;
    const float* S = g_Spre + (size_t)b * NN * NN;
    float* E = g_Sexp + (size_t)b * NN * NN;
    float mx = g_cmax[b * NN + m0 + lane];
    float s = 0.f;
    for (int n = w; n < NN; n += 8) {
        size_t i = (size_t)n * NN + m0 + lane;
        float v = __expf(S[i] - mx);
        E[i] = v;
        s += v;
    }
    __shared__ float red[8][32];
    red[w][lane] = s;
    __syncthreads();
    if (w == 0) {
        float v = red[0][lane];
        #pragma unroll
        for (int i = 1; i < 8; i++) v += red[i][lane];
        g_icsum[b * NN + m0 + lane] = 1.0f / v;
    }
}

// ---------------------------------------------------------------------------
// K11a: AT for all 3 k per CTA (Sexp tile read once)      grid(16,16,16) x 256
// ---------------------------------------------------------------------------
__global__ void __launch_bounds__(256) k_mkA3(const float* __restrict__ cheb) {
    int b = blockIdx.z;
    int mtile = blockIdx.y * 64;
    int ntile = blockIdx.x * 64;
    __shared__ float tS[64][65];
    __shared__ float tC[64][65];
    __shared__ float ics[64];
    int tid = threadIdx.x;
    const float* Sx = g_Sexp + (size_t)b * NN * NN;
    if (tid < 64) ics[tid] = g_icsum[b * NN + mtile + tid];
    #pragma unroll
    for (int i = 0; i < 4; i++) {
        int idx = tid + i * 256;
        int n_loc = idx >> 4, m_loc = (idx & 15) * 4;
        size_t g = (size_t)(ntile + n_loc) * NN + mtile + m_loc;
        float4 sv = *(const float4*)&Sx[g];
        tS[m_loc + 0][n_loc] = sv.x;
        tS[m_loc + 1][n_loc] = sv.y;
        tS[m_loc + 2][n_loc] = sv.z;
        tS[m_loc + 3][n_loc] = sv.w;
    }
    __syncthreads();
    for (int kk = 0; kk < NK; kk++) {
        const float* Cb = cheb + (size_t)kk * NN * NN;
        #pragma unroll
        for (int i = 0; i < 4; i++) {
            int idx = tid + i * 256;
            int n_loc = idx >> 4, m_loc = (idx & 15) * 4;
            size_t g = (size_t)(ntile + n_loc) * NN + mtile + m_loc;
            float4 cv = *(const float4*)&Cb[g];
            tC[m_loc + 0][n_loc] = cv.x;
            tC[m_loc + 1][n_loc] = cv.y;
            tC[m_loc + 2][n_loc] = cv.z;
            tC[m_loc + 3][n_loc] = cv.w;
        }
        __syncthreads();
        int m_loc = tid >> 2, q = tid & 3;
        float icm = ics[m_loc];
        unsigned short uh[16], ul[16];
        #pragma unroll
        for (int u = 0; u < 16; u++)
            split_bf(tS[m_loc][q * 16 + u] * tC[m_loc][q * 16 + u] * icm,
                     uh[u], ul[u]);
        uint32_t wh[8], wl[8];
        #pragma unroll
        for (int p = 0; p < 8; p++) {
            wh[p] = (uint32_t)uh[2 * p] | ((uint32_t)uh[2 * p + 1] << 16);
            wl[p] = (uint32_t)ul[2 * p] | ((uint32_t)ul[2 * p + 1] << 16);
        }
        size_t off = ((size_t)(b * 3 + kk) * NN + mtile + m_loc) * NN + ntile + q * 16;
        uint4* dh = (uint4*)(g_AT_hi + off);
        uint4* dl = (uint4*)(g_AT_lo + off);
        dh[0] = make_uint4(wh[0], wh[1], wh[2], wh[3]);
        dh[1] = make_uint4(wh[4], wh[5], wh[6], wh[7]);
        dl[0] = make_uint4(wl[0], wl[1], wl[2], wl[3]);
        dl[1] = make_uint4(wl[4], wl[5], wl[6], wl[7]);
        __syncthreads();
    }
}

// ---------------------------------------------------------------------------
// K11b: XT[b][j][n] = bf16split( x[b][n][j] )             grid(16,12,16) x 256
// ---------------------------------------------------------------------------
__global__ void __launch_bounds__(256) k_mkX(const float* __restrict__ x) {
    int b = blockIdx.z;
    int jtile = blockIdx.y * 64;
    int ntile = blockIdx.x * 64;
    __shared__ float tile[64][65];
    int tid = threadIdx.x;
    #pragma unroll
    for (int i = 0; i < 4; i++) {
        int idx = tid + i * 256;
        int n_loc = idx >> 4, j_loc = (idx & 15) * 4;
        size_t g = (size_t)(b * NN + ntile + n_loc) * FT + jtile + j_loc;
        float4 v = *(const float4*)&x[g];
        tile[j_loc + 0][n_loc] = v.x;
        tile[j_loc + 1][n_loc] = v.y;
        tile[j_loc + 2][n_loc] = v.z;
        tile[j_loc + 3][n_loc] = v.w;
    }
    __syncthreads();
    int j_loc = tid >> 2, q = tid & 3;
    unsigned short uh[16], ul[16];
    #pragma unroll
    for (int u = 0; u < 16; u++)
        split_bf(tile[j_loc][q * 16 + u], uh[u], ul[u]);
    uint32_t wh[8], wl[8];
    #pragma unroll
    for (int p = 0; p < 8; p++) {
        wh[p] = (uint32_t)uh[2 * p] | ((uint32_t)uh[2 * p + 1] << 16);
        wl[p] = (uint32_t)ul[2 * p] | ((uint32_t)ul[2 * p + 1] << 16);
    }
    size_t off = ((size_t)b * FT + jtile + j_loc) * NN + ntile + q * 16;
    uint4* dh = (uint4*)(g_XT_hi + off);
    uint4* dl = (uint4*)(g_XT_lo + off);
    dh[0] = make_uint4(wh[0], wh[1], wh[2], wh[3]);
    dh[1] = make_uint4(wh[4], wh[5], wh[6], wh[7]);
    dl[0] = make_uint4(wl[0], wl[1], wl[2], wl[3]);
    dl[1] = make_uint4(wl[4], wl[5], wl[6], wl[7]);
}

// ---------------------------------------------------------------------------
// K12 (dominant): mma.sync bf16 GEMM, 3-term compensated.
//   Stage = one KC=32 chunk with Ah+Al+Xh+Xl; all 3 terms per stage.
//   CTA 128m x 128j, 8 warps, 32 stages, double buffer (80KB smem, 2 CTA/SM).
//   grid(6, 8, 48) x 256
// ---------------------------------------------------------------------------
constexpr int STG = 10240;            // 128 rows * 80B per matrix
constexpr int STAGE_BYTES = 4 * STG;  // 40960
constexpr int MMA_SMEM = 2 * STAGE_BYTES;

__global__ void __launch_bounds__(256, 2) k_mma2() {
    extern __shared__ __align__(16) unsigned char smb[];
    int tid = threadIdx.x, lane = tid & 31, wid = tid >> 5;
    int kb = blockIdx.z;
    int b = kb / 3, kk = kb - b * 3;
    int m0 = blockIdx.y * 128;
    int j0 = blockIdx.x * 128;
    const unsigned short* Ah = g_AT_hi + (size_t)kb * NN * NN + (size_t)m0 * NN;
    const unsigned short* Al = g_AT_lo + (size_t)kb * NN * NN + (size_t)m0 * NN;
    const unsigned short* Xh = g_XT_hi + (size_t)b * FT * NN + (size_t)j0 * NN;
    const unsigned short* Xl = g_XT_lo + (size_t)b * FT * NN + (size_t)j0 * NN;
    int warp_m = wid >> 2, warp_j = wid & 3;

    float d[4][4][4];
    #pragma unroll
    for (int i = 0; i < 4; i++)
        #pragma unroll
        for (int j = 0; j < 4; j++)
            #pragma unroll
            for (int q = 0; q < 4; q++) d[i][j][q] = 0.f;

    int arow = (lane < 16) ? lane : (lane - 16);
    int ako  = (lane < 16) ? 0 : 8;
    int brow = (lane & 7) + ((lane >> 4) << 3);
    int bko  = (lane & 8) ? 8 : 0;

    auto issue = [&](int s) {
        unsigned char* buf = smb + (s & 1) * STAGE_BYTES;
        int n0 = s * 32;
        const unsigned short* srcs[4] = {Ah + n0, Al + n0, Xh + n0, Xl + n0};
        #pragma unroll
        for (int i = 0; i < 8; i++) {
            int mat = i >> 1;
            int idx = tid + (i & 1) * 256;
            int r = idx >> 2, c = idx & 3;
            cpasync16(smem_u32(buf + mat * STG + r * 80 + c * 16),
                      srcs[mat] + (size_t)r * NN + c * 8);
        }
        asm volatile("cp.async.commit_group;" ::: "memory");
    };

    issue(0);
    for (int s = 0; s < 32; s++) {
        if (s + 1 < 32) {
            issue(s + 1);
            asm volatile("cp.async.wait_group 1;" ::: "memory");
        } else {
            asm volatile("cp.async.wait_group 0;" ::: "memory");
        }
        __syncthreads();
        unsigned char* buf = smb + (s & 1) * STAGE_BYTES;
        uint32_t aH = smem_u32(buf);
        uint32_t aL = aH + STG;
        uint32_t xH = aH + 2 * STG;
        uint32_t xL = aH + 3 * STG;
        #pragma unroll
        for (int ks = 0; ks < 2; ks++) {
            uint32_t afr[4][4], bh[2][4], bl[2][4];
            #pragma unroll
            for (int mt = 0; mt < 4; mt++)
                ldmx4(afr[mt], aH + (warp_m * 64 + mt * 16 + arow) * 80 +
                               (ks * 16 + ako) * 2);
            #pragma unroll
            for (int jp = 0; jp < 2; jp++)
                ldmx4(bh[jp], xH + (warp_j * 32 + jp * 16 + brow) * 80 +
                              (ks * 16 + bko) * 2);
            #pragma unroll
            for (int jp = 0; jp < 2; jp++)
                ldmx4(bl[jp], xL + (warp_j * 32 + jp * 16 + brow) * 80 +
                              (ks * 16 + bko) * 2);
            #pragma unroll
            for (int mt = 0; mt < 4; mt++)
                #pragma unroll
                for (int jt = 0; jt < 4; jt++)
                    mma16816(d[mt][jt], afr[mt],
                             bh[jt >> 1][2 * (jt & 1)], bh[jt >> 1][2 * (jt & 1) + 1]);
            #pragma unroll
            for (int mt = 0; mt < 4; mt++)
                #pragma unroll
                for (int jt = 0; jt < 4; jt++)
                    mma16816(d[mt][jt], afr[mt],
                             bl[jt >> 1][2 * (jt & 1)], bl[jt >> 1][2 * (jt & 1) + 1]);
            #pragma unroll
            for (int mt = 0; mt < 4; mt++)
                ldmx4(afr[mt], aL + (warp_m * 64 + mt * 16 + arow) * 80 +
                               (ks * 16 + ako) * 2);
            #pragma unroll
            for (int mt = 0; mt < 4; mt++)
                #pragma unroll
                for (int jt = 0; jt < 4; jt++)
                    mma16816(d[mt][jt], afr[mt],
                             bh[jt >> 1][2 * (jt & 1)], bh[jt >> 1][2 * (jt & 1) + 1]);
        }
        __syncthreads();
    }

    float* ob = g_rhs_all + (size_t)(kk * NB + b) * NN * FT;
    int mb = m0 + warp_m * 64, jb = j0 + warp_j * 32;
    #pragma unroll
    for (int mt = 0; mt < 4; mt++)
        #pragma unroll
        for (int jt = 0; jt < 4; jt++) {
            int row = mb + mt * 16 + (lane >> 2);
            int col = jb + jt * 8 + 2 * (lane & 3);
            float2 v0; v0.x = d[mt][jt][0]; v0.y = d[mt][jt][1];
            float2 v1; v1.x = d[mt][jt][2]; v1.y = d[mt][jt][3];
            *(float2*)&ob[(size_t)row * FT + col] = v0;
            *(float2*)&ob[(size_t)(row + 8) * FT + col] = v1;
        }
}

// ---------------------------------------------------------------------------
// K13: fused tail, 4 nodes/CTA, weights via LDG, 63KB smem -> 3 CTA/SM.
//   grid(256,16) x 256
// ---------------------------------------------------------------------------
constexpr int TAIL_SMEM_FLOATS = 6656 + 3072 + 6144 + 256;  // 16128 -> 64512B

__global__ void __launch_bounds__(256, 3) k_tail(
    const float* __restrict__ x, const float* __restrict__ Theta,
    const float* __restrict__ tcb, const float* __restrict__ rcb,
    const float* __restrict__ gma, const float* __restrict__ bet,
    float* __restrict__ out) {
    extern __shared__ float smf[];
    float* SG = smf;           // [m(4)][cc(64)][26]  6656
    float* Xs = SG + 6656;     // [m][768]            3072
    float* Z  = Xs + 3072;     // [m][1536]           6144
    float* Bc = Z + 6144;
    float* Br = Bc + 64;
    float* Ga = Br + 64;
    float* Be = Ga + 64;

    int b = blockIdx.y, m0 = blockIdx.x * 4;
    int tid = threadIdx.x;
    if (tid < 64) { Bc[tid] = tcb[tid]; Br[tid] = rcb[tid]; Ga[tid] = gma[tid]; Be[tid] = bet[tid]; }
    for (int i = tid; i < 6656; i += 256) SG[i] = 0.f;
    for (int e = tid; e < 3072; e += 256) {
        int m = e / 768, ft = e - m * 768;
        Xs[e] = x[((size_t)(b * NN + m0 + m)) * FT + ft];
    }
    __syncthreads();

    // Phase 1: sg = relu(Theta contraction). 192 units = m(4) x tg(6) x og(8)
    if (tid < 192) {
        int m = tid / 48, rr = tid - m * 48;
        int tg = rr >> 3, og = rr & 7;
        int t0 = tg * 4, o0 = og * 8;
        unsigned long long acc[4][4];
        #pragma unroll
        for (int i = 0; i < 4; i++)
            #pragma unroll
            for (int p = 0; p < 4; p++) acc[i][p] = 0ull;
        #pragma unroll
        for (int k = 0; k < NK; k++) {
            const float* gr = g_rhs_all +
                ((size_t)(k * NB + b) * NN + m0 + m) * FT;
            const float* th = Theta + k * 2048 + o0;
            #pragma unroll 4
            for (int f = 0; f < NF; f++) {
                float4 bk = *(const float4*)&gr[f * 24 + t0];
                const unsigned long long* tp =
                    (const unsigned long long*)(th + f * 64);
                unsigned long long bp0 = pack2(bk.x), bp1 = pack2(bk.y);
                unsigned long long bp2 = pack2(bk.z), bp3 = pack2(bk.w);
                #pragma unroll
                for (int p = 0; p < 4; p++) {
                    unsigned long long tv = tp[p];
                    ffma2(acc[0][p], bp0, tv);
                    ffma2(acc[1][p], bp1, tv);
                    ffma2(acc[2][p], bp2, tv);
                    ffma2(acc[3][p], bp3, tv);
                }
            }
        }
        #pragma unroll
        for (int p = 0; p < 4; p++) {
            int o = o0 + 2 * p;
            #pragma unroll
            for (int i = 0; i < 4; i++) {
                SG[(m * 64 + o) * 26 + t0 + i + 1] = fmaxf(lo32(acc[i][p]), 0.f);
                SG[(m * 64 + o + 1) * 26 + t0 + i + 1] = fmaxf(hi32(acc[i][p]), 0.f);
            }
        }
    }
    __syncthreads();

    // Phase 2: z = relu(timeconv + residual). 512 units = m(4) x tg(8,3t) x cg(16,4c)
    #pragma unroll
    for (int rep = 0; rep < 2; rep++) {
        int u = tid + rep * 256;
        int m = u >> 7, rr = u & 127;
        int tg = rr >> 4, cg = rr & 15;
        int t0 = tg * 3, c0 = cg * 4;
        unsigned long long z[3][2];
        #pragma unroll
        for (int i = 0; i < 3; i++) { z[i][0] = 0ull; z[i][1] = 0ull; }
        const float* sgm = &SG[m * 1664];
        for (int cc = 0; cc < NCC; cc++) {
            const float* srow = &sgm[cc * 26 + t0];
            unsigned long long sp[5];
            #pragma unroll
            for (int j = 0; j < 5; j++) sp[j] = pack2(srow[j]);
            const float* wbase = &g_Wt[cc * 192 + c0];
            #pragma unroll
            for (int r = 0; r < 3; r++) {
                const unsigned long long* wp =
                    (const unsigned long long*)(wbase + r * 64);
                unsigned long long w0 = wp[0], w1 = wp[1];
                #pragma unroll
                for (int i = 0; i < 3; i++) {
                    ffma2(z[i][0], sp[i + r], w0);
                    ffma2(z[i][1], sp[i + r], w1);
                }
            }
        }
        const float* xm = &Xs[m * 768];
        #pragma unroll 4
        for (int f = 0; f < NF; f++) {
            const float* xr = &xm[f * 24 + t0];
            unsigned long long xp0 = pack2(xr[0]);
            unsigned long long xp1 = pack2(xr[1]);
            unsigned long long xp2 = pack2(xr[2]);
            const unsigned long long* wp =
                (const unsigned long long*)(&g_Wr[f * 64 + c0]);
            unsigned long long w0 = wp[0], w1 = wp[1];
            ffma2(z[0][0], xp0, w0); ffma2(z[0][1], xp0, w1);
            ffma2(z[1][0], xp1, w0); ffma2(z[1][1], xp1, w1);
            ffma2(z[2][0], xp2, w0); ffma2(z[2][1], xp2, w1);
        }
        float* zb = &Z[m * 1536];
        #pragma unroll
        for (int p = 0; p < 2; p++) {
            int c = c0 + 2 * p;
            float b0 = Bc[c] + Br[c], b1 = Bc[c + 1] + Br[c + 1];
            #pragma unroll
            for (int i = 0; i < 3; i++) {
                zb[c * 24 + t0 + i] = fmaxf(lo32(z[i][p]) + b0, 0.f);
                zb[(c + 1) * 24 + t0 + i] = fmaxf(hi32(z[i][p]) + b1, 0.f);
            }
        }
    }
    __syncthreads();

    // Phase 3: LayerNorm over ct, write out[b,m,ct,t]
    if (tid < 96) {
        int m = tid / 24, t = tid - m * 24;
        const float* zz = &Z[m * 1536 + t];
        float mu = 0.f;
        #pragma unroll
        for (int c = 0; c < NCT; c++) mu += zz[c * NT];
        mu *= (1.f / 64.f);
        float var = 0.f;
        #pragma unroll
        for (int c = 0; c < NCT; c++) { float dd = zz[c * NT] - mu; var += dd * dd; }
        var *= (1.f / 64.f);
        float rs = rsqrtf(var + 1e-5f);
        float* op = out + ((size_t)(b * NN + m0 + m) * NCT) * NT + t;
        #pragma unroll
        for (int c = 0; c < NCT; c++)
            op[c * NT] = (zz[c * NT] - mu) * rs * Ga[c] + Be[c];
    }
}

// ---------------------------------------------------------------------------
extern "C" void kernel_launch(void* const* d_in, const int* in_sizes, int n_in,
                              void* d_out, int out_size) {
    const float* x     = (const float*)d_in[0];
    const float* W1    = (const float*)d_in[1];
    const float* W2    = (const float*)d_in[2];
    const float* W3    = (const float*)d_in[3];
    const float* U1    = (const float*)d_in[4];
    const float* U2    = (const float*)d_in[5];
    const float* U3    = (const float*)d_in[6];
    const float* cheb  = (const float*)d_in[7];
    const float* Theta = (const float*)d_in[8];
    const float* tc_w  = (const float*)d_in[9];
    const float* tc_b  = (const float*)d_in[10];
    const float* rc_w  = (const float*)d_in[11];
    const float* rc_b  = (const float*)d_in[12];
    const float* gamma = (const float*)d_in[13];
    const float* beta  = (const float*)d_in[14];
    float* out = (float*)d_out;

    cudaFuncSetAttribute(k_tail, cudaFuncAttributeMaxDynamicSharedMemorySize,
                         TAIL_SMEM_FLOATS * 4);
    cudaFuncSetAttribute(k_mma2, cudaFuncAttributeMaxDynamicSharedMemorySize,
                         MMA_SMEM);

    k_prep_w<<<1, 256>>>(tc_w, rc_w);
    // temporal attention
    k_lhs_p<<<dim3(8, NB), 256>>>(x, U1);
    k_lhs_red<<<NB, 256>>>();
    k_rhs_t<<<dim3(NN / 32, NB), 256>>>(x, U3);
    k_epre<<<dim3(NT, NB), 256>>>(U2);
    k_esm<<<dim3(NT, NB), 32>>>();
    k_ew1<<<NB, 32>>>(W1);
    // spatial attention (x_TAt folded out)
    k_lhs2<<<NB * 128, 256>>>(x, W2);
    k_xw3<<<dim3(NN / 32, NB), 256>>>(x, W3);
    k_rhs_s2<<<dim3(NN / 32, NB), 256>>>();
    k_spre<<<dim3(16, 16, NB), 256>>>();
    k_cmax<<<dim3(NN / 32, NB), 256>>>();
    k_sexp<<<dim3(NN / 32, NB), 256>>>();
    // operand prep for tensor-core GEMM
    k_mkA3<<<dim3(16, 16, NB), 256>>>(cheb);
    k_mkX<<<dim3(16, 12, NB), 256>>>(x);
    // chebyshev graph conv on mma.sync
    k_mma2<<<dim3(6, 8, NB * NK), 256, MMA_SMEM>>>();
    // fused Theta + timeconv + residual + LN
    k_tail<<<dim3(NN / 4, NB), 256, TAIL_SMEM_FLOATS * 4>>>(
        x, Theta, tc_b, rc_b, gamma, beta, out);
}

// round 16
// speedup vs baseline: 3.0508x; 1.2074x over previous
#include <cuda_runtime.h>
#include <cuda_bf16.h>
#include <cuda_fp16.h>
#include <cstdint>
#include <cstddef>

// ---------------------------------------------------------------------------
// ASTGCN block. B=16, N=1024, F=32, T=24, K=3, CC=CT=64.
// Cheb-GEMM: 2-term fp16 compensated mma.sync (A scaled 2^10, hi-only).
// ---------------------------------------------------------------------------

constexpr int NB  = 16;
constexpr int NN  = 1024;
constexpr int NF  = 32;
constexpr int NT  = 24;
constexpr int NK  = 3;
constexpr int NCC = 64;
constexpr int NCT = 64;
constexpr int FT  = NF * NT;   // 768

constexpr float A_SCALE   = 1024.0f;
constexpr float A_UNSCALE = 1.0f / 1024.0f;

// ------------------------- scratch (device globals) ------------------------
__device__ float g_lpart[NB * 32 * FT];
__device__ float g_lhs_t[NB * NT * NF];
__device__ float g_rhs_t[NB * NN * NT];
__device__ float g_Epre[NB * NT * NT];
__device__ float g_E[NB * NT * NT];
__device__ float g_ew1[NB * NT];
__device__ float g_xw3[NB * NN * NT];
__device__ float g_lhs2s[NB * NN * NT];
__device__ float g_rhs_s[NB * NT * NN];
__device__ float g_Spre[(size_t)NB * NN * NN];
__device__ float g_cmax[NB * NN];
__device__ float g_icsum[NB * NN];
__device__ __align__(16) unsigned short g_AT[(size_t)NK * NB * NN * NN];  // fp16 [b*3+k][m][n], x1024
__device__ __align__(16) unsigned short g_XT_hi[(size_t)NB * FT * NN];    // fp16 [b][j][n]
__device__ __align__(16) unsigned short g_XT_lo[(size_t)NB * FT * NN];
__device__ __align__(16) float g_rhs_all[(size_t)NK * NB * NN * FT];  // [(k*NB+b)][m][ft]
__device__ __align__(16) float g_Wt[12288];   // [cc][r][ct]
__device__ __align__(16) float g_Wr[2048];    // [f][ct]

// ------------------------------ helpers ------------------------------------
__device__ __forceinline__ uint32_t smem_u32(const void* p) {
    uint32_t a;
    asm("{ .reg .u64 t; cvta.to.shared.u64 t, %1; cvt.u32.u64 %0, t; }"
        : "=r"(a) : "l"(p));
    return a;
}
__device__ __forceinline__ void ffma2(unsigned long long& d,
                                      unsigned long long a,
                                      unsigned long long b) {
    asm("fma.rn.f32x2 %0, %1, %2, %0;" : "+l"(d) : "l"(a), "l"(b));
}
__device__ __forceinline__ unsigned long long pack2(float x) {
    unsigned long long r;
    asm("mov.b64 %0, {%1, %1};" : "=l"(r) : "f"(x));
    return r;
}
__device__ __forceinline__ float lo32(unsigned long long v) {
    return __uint_as_float((unsigned)(v & 0xffffffffull));
}
__device__ __forceinline__ float hi32(unsigned long long v) {
    return __uint_as_float((unsigned)(v >> 32));
}
__device__ __forceinline__ void ldmx4(uint32_t* r, uint32_t a) {
    asm volatile("ldmatrix.sync.aligned.m8n8.x4.shared.b16 {%0,%1,%2,%3}, [%4];"
                 : "=r"(r[0]), "=r"(r[1]), "=r"(r[2]), "=r"(r[3]) : "r"(a));
}
__device__ __forceinline__ void mma16816h(float* d, const uint32_t* a,
                                          uint32_t b0, uint32_t b1) {
    asm volatile(
        "mma.sync.aligned.m16n8k16.row.col.f32.f16.f16.f32 "
        "{%0,%1,%2,%3}, {%4,%5,%6,%7}, {%8,%9}, {%0,%1,%2,%3};"
        : "+f"(d[0]), "+f"(d[1]), "+f"(d[2]), "+f"(d[3])
        : "r"(a[0]), "r"(a[1]), "r"(a[2]), "r"(a[3]), "r"(b0), "r"(b1));
}
__device__ __forceinline__ void cpasync16(uint32_t dst, const void* src) {
    asm volatile("cp.async.cg.shared.global [%0], [%1], 16;"
                 :: "r"(dst), "l"(src) : "memory");
}
__device__ __forceinline__ void split_h(float v, unsigned short& h,
                                        unsigned short& l) {
    __half hh = __float2half_rn(v);
    float r = v - __half2float(hh);
    __half hl = __float2half_rn(r);
    h = __half_as_ushort(hh);
    l = __half_as_ushort(hl);
}

// ---------------------------------------------------------------------------
// K0: transpose conv weights for the tail                 <<<1,256>>>
// ---------------------------------------------------------------------------
__global__ void __launch_bounds__(256) k_prep_w(const float* __restrict__ tcw,
                                                const float* __restrict__ rcw) {
    int tid = threadIdx.x;
    for (int i = tid; i < 12288; i += 256) {
        int cc = i / 192, rem = i - cc * 192;
        int r = rem >> 6, ct = rem & 63;
        g_Wt[i] = tcw[ct * 192 + cc * 3 + r];
    }
    for (int i = tid; i < 2048; i += 256) {
        int f = i >> 6, ct = i & 63;
        g_Wr[i] = rcw[ct * 32 + f];
    }
}

// ---------------------------------------------------------------------------
// K1: fused x-reader: lhs_t partials + rhs_t + xw3 (x read ONCE)
//   grid(32, 16) x 256, 98.4KB dynamic smem
// ---------------------------------------------------------------------------
__global__ void __launch_bounds__(256) k_rx(const float* __restrict__ x,
                                            const float* __restrict__ U1,
                                            const float* __restrict__ U3,
                                            const float* __restrict__ W3) {
    int nb = blockIdx.x, b = blockIdx.y;
    int n0 = nb * 32;
    extern __shared__ float xs[];  // [32][769]
    __shared__ float U1s[32], U3s[32], W3s[32];
    int tid = threadIdx.x;
    if (tid < 32) { U1s[tid] = U1[n0 + tid]; U3s[tid] = U3[tid]; W3s[tid] = W3[tid]; }
    const float* xb = x + ((size_t)(b * NN + n0)) * FT;  // 32x768 contiguous
    #pragma unroll
    for (int i = 0; i < 24; i++) {
        int e = (tid + i * 256) * 4;
        float4 v = *(const float4*)&xb[e];
        int r = e / 768, c = e - r * 768;
        float* d = &xs[r * 769 + c];
        d[0] = v.x; d[1] = v.y; d[2] = v.z; d[3] = v.w;
    }
    __syncthreads();
    // rhs_t[n,t] = sum_f U3[f]*x ; xw3[n,t] = sum_f W3[f]*x
    float* ort = g_rhs_t + (size_t)b * NN * NT + (size_t)n0 * NT;
    float* oxw = g_xw3 + (size_t)b * NN * NT + (size_t)n0 * NT;
    #pragma unroll
    for (int i = 0; i < 3; i++) {
        int e = tid + i * 256;
        int n = e / 24, t = e - n * 24;
        float a = 0.f, c2 = 0.f;
        #pragma unroll
        for (int f = 0; f < NF; f++) {
            float v = xs[n * 769 + f * 24 + t];
            a += U3s[f] * v;
            c2 += W3s[f] * v;
        }
        ort[e] = a; oxw[e] = c2;
    }
    // lhs partial: sum_n U1[n]*x[n,ft]
    #pragma unroll
    for (int i = 0; i < 3; i++) {
        int ft = tid + i * 256;
        float v = 0.f;
        #pragma unroll
        for (int n = 0; n < 32; n++) v += U1s[n] * xs[n * 769 + ft];
        g_lpart[((size_t)b * 32 + nb) * FT + ft] = v;
    }
}

// K1b: reduce 32 partials -> lhs_t[b,t,f]                 grid(16) x 256
__global__ void __launch_bounds__(256) k_lhs_red() {
    int b = blockIdx.x, tid = threadIdx.x;
    for (int ft = tid; ft < FT; ft += 256) {
        float v = 0.f;
        #pragma unroll
        for (int nb = 0; nb < 32; nb++) v += g_lpart[((size_t)b * 32 + nb) * FT + ft];
        int f = ft / NT, t = ft - f * NT;
        g_lhs_t[(b * NT + t) * NF + f] = v;
    }
}

// ---------------------------------------------------------------------------
// K3: E_pre
// ---------------------------------------------------------------------------
__global__ void __launch_bounds__(256) k_epre(const float* __restrict__ U2) {
    int t = blockIdx.x, b = blockIdx.y;
    __shared__ float lt[NF];
    __shared__ float red[8][NT];
    int tid = threadIdx.x;
    if (tid < NF) lt[tid] = g_lhs_t[(b * NT + t) * NF + tid];
    __syncthreads();
    float pe[NT];
    #pragma unroll
    for (int s = 0; s < NT; s++) pe[s] = 0.f;
    for (int n = tid; n < NN; n += 256) {
        float l2 = 0.f;
        #pragma unroll
        for (int f = 0; f < NF; f++) l2 += lt[f] * U2[f * NN + n];
        const float* rr = &g_rhs_t[((size_t)b * NN + n) * NT];
        #pragma unroll
        for (int s = 0; s < NT; s++) pe[s] += l2 * rr[s];
    }
    int lane = tid & 31, w = tid >> 5;
    #pragma unroll
    for (int s = 0; s < NT; s++) {
        float v = pe[s];
        #pragma unroll
        for (int o = 16; o; o >>= 1) v += __shfl_xor_sync(0xffffffffu, v, o);
        if (lane == 0) red[w][s] = v;
    }
    __syncthreads();
    if (tid < NT) {
        float v = 0.f;
        #pragma unroll
        for (int w2 = 0; w2 < 8; w2++) v += red[w2][tid];
        g_Epre[b * NT * NT + t * NT + tid] = v;
    }
}

// ---------------------------------------------------------------------------
// K4: E = softmax(E_pre, axis=t)
// ---------------------------------------------------------------------------
__global__ void k_esm() {
    int s = blockIdx.x, b = blockIdx.y, lane = threadIdx.x;
    float v = (lane < NT) ? g_Epre[b * NT * NT + lane * NT + s] : -3.4e38f;
    float mx = v;
    #pragma unroll
    for (int o = 16; o; o >>= 1) mx = fmaxf(mx, __shfl_xor_sync(0xffffffffu, mx, o));
    float e = (lane < NT) ? __expf(v - mx) : 0.f;
    float sm = e;
    #pragma unroll
    for (int o = 16; o; o >>= 1) sm += __shfl_xor_sync(0xffffffffu, sm, o);
    if (lane < NT) g_E[b * NT * NT + lane * NT + s] = e / sm;
}

// ---------------------------------------------------------------------------
// K4b: ew1[b,t] = sum_s E[b,t,s] * W1[s]                  <<<16,32>>>
// ---------------------------------------------------------------------------
__global__ void k_ew1(const float* __restrict__ W1) {
    int b = blockIdx.x, lane = threadIdx.x;
    if (lane < NT) {
        float s = 0.f;
        #pragma unroll
        for (int t = 0; t < NT; t++) s += g_E[b * 576 + lane * NT + t] * W1[t];
        g_ew1[b * NT + lane] = s;
    }
}

// ---------------------------------------------------------------------------
// K6: lhs2s[b,n,t'] = sum_f (sum_t x[b,n,f,t] ew1[b,t]) W2[f,t']
// ---------------------------------------------------------------------------
__global__ void __launch_bounds__(256) k_lhs2(const float* __restrict__ x,
                                              const float* __restrict__ W2) {
    int bb = blockIdx.x;
    int b = bb >> 7;
    int n0 = (bb & 127) * 8;
    __shared__ float ls[8][NF];
    __shared__ float ew1s[NT];
    int tid = threadIdx.x;
    if (tid < NT) ew1s[tid] = g_ew1[b * NT + tid];
    __syncthreads();
    int ni = tid >> 5, f = tid & 31;
    const float* r = x + ((size_t)(b * NN + n0 + ni)) * FT + f * NT;
    float s = 0.f;
    #pragma unroll
    for (int t = 0; t < NT; t++) s += r[t] * ew1s[t];
    ls[ni][f] = s;
    __syncthreads();
    if (tid < 8 * NT) {
        int ni2 = tid / NT, t = tid - ni2 * NT;
        float v = 0.f;
        #pragma unroll
        for (int ff = 0; ff < NF; ff++) v += ls[ni2][ff] * W2[ff * NT + t];
        g_lhs2s[((size_t)b * NN + n0 + ni2) * NT + t] = v;
    }
}

// ---------------------------------------------------------------------------
// K7b: rhs_s[b,t,m] = sum_s xw3[b,m,s] * E[b,s,t]         grid(32,16) x 256
// ---------------------------------------------------------------------------
__global__ void __launch_bounds__(256) k_rhs_s2() {
    int b = blockIdx.y, m0 = blockIdx.x * 32;
    int tid = threadIdx.x;
    __shared__ float xs[768];
    __shared__ float Es[576];
    for (int i = tid; i < 768; i += 256)
        xs[i] = g_xw3[(size_t)b * NN * NT + (size_t)m0 * NT + i];
    for (int i = tid; i < 576; i += 256) Es[i] = g_E[b * 576 + i];
    __syncthreads();
    #pragma unroll
    for (int i = 0; i < 3; i++) {
        int e = tid + i * 256;
        int m = e / 24, t = e - m * 24;
        float v = 0.f;
        #pragma unroll
        for (int s = 0; s < NT; s++) v += xs[m * 24 + s] * Es[s * 24 + t];
        g_rhs_s[(size_t)b * NT * NN + (size_t)t * NN + m0 + m] = v;
    }
}

// ---------------------------------------------------------------------------
// K8: S_pre GEMM
// ---------------------------------------------------------------------------
__global__ void __launch_bounds__(256) k_spre() {
    int b = blockIdx.z;
    int mtile = blockIdx.x * 64;
    int ntile = blockIdx.y * 64;
    __shared__ __align__(16) float Ls[64 * 25];
    __shared__ __align__(16) float Rs[24 * 64];
    int tid = threadIdx.x;
    const float* L = g_lhs2s + (size_t)b * NN * NT;
    const float* R = g_rhs_s + (size_t)b * NT * NN;
    #pragma unroll
    for (int i = 0; i < 6; i++) {
        int e = tid + i * 256;
        int nn = e / 24, tt = e - nn * 24;
        Ls[nn * 25 + tt] = L[(size_t)(ntile + nn) * NT + tt];
        int t2 = e >> 6, m2 = e & 63;
        Rs[e] = R[(size_t)t2 * NN + mtile + m2];
    }
    __syncthreads();
    int tx = tid & 15, ty = tid >> 4;
    float acc[4][4];
    #pragma unroll
    for (int i = 0; i < 4; i++)
        #pragma unroll
        for (int j = 0; j < 4; j++) acc[i][j] = 0.f;
    #pragma unroll
    for (int kk = 0; kk < NT; kk++) {
        float a[4], bb[4];
        #pragma unroll
        for (int i = 0; i < 4; i++) a[i] = Ls[(ty * 4 + i) * 25 + kk];
        float4 rv = *(const float4*)&Rs[kk * 64 + tx * 4];
        bb[0] = rv.x; bb[1] = rv.y; bb[2] = rv.z; bb[3] = rv.w;
        #pragma unroll
        for (int i = 0; i < 4; i++)
            #pragma unroll
            for (int j = 0; j < 4; j++) acc[i][j] += a[i] * bb[j];
    }
    float* S = g_Spre + (size_t)b * NN * NN;
    #pragma unroll
    for (int i = 0; i < 4; i++) {
        float4 o;
        o.x = acc[i][0]; o.y = acc[i][1]; o.z = acc[i][2]; o.w = acc[i][3];
        *(float4*)&S[(size_t)(ntile + ty * 4 + i) * NN + mtile + tx * 4] = o;
    }
}

// ---------------------------------------------------------------------------
// K9: fused colmax + colsum(exp): one DRAM pass (2nd pass L2-hot)
//   grid(32,16) x 256
// ---------------------------------------------------------------------------
__global__ void __launch_bounds__(256) k_cms() {
    int b = blockIdx.y, m0 = blockIdx.x * 32;
    int tid = threadIdx.x, w = tid >> 5, lane = tid & 31;
    const float* S = g_Spre + (size_t)b * NN * NN;
    float mx = -3.4e38f;
    for (int n = w; n < NN; n += 8)
        mx = fmaxf(mx, S[(size_t)n * NN + m0 + lane]);
    __shared__ float red[8][32];
    __shared__ float mxs[32];
    red[w][lane] = mx;
    __syncthreads();
    if (w == 0) {
        float v = red[0][lane];
        #pragma unroll
        for (int i = 1; i < 8; i++) v = fmaxf(v, red[i][lane]);
        mxs[lane] = v;
        g_cmax[b * NN + m0 + lane] = v;
    }
    __syncthreads();
    float m = mxs[lane];
    float s = 0.f;
    for (int n = w; n < NN; n += 8)
        s += __expf(S[(size_t)n * NN + m0 + lane] - m);
    __syncthreads();
    red[w][lane] = s;
    __syncthreads();
    if (w == 0) {
        float v = red[0][lane];
        #pragma unroll
        for (int i = 1; i < 8; i++) v += red[i][lane];
        g_icsum[b * NN + m0 + lane] = 1.0f / v;
    }
}

// ---------------------------------------------------------------------------
// K11a: AT[kb][m][n] = fp16( exp(Spre-cmax)*cheb*icsum*1024 ), all 3 k/CTA
//   grid(16,16,16) x 256
// ---------------------------------------------------------------------------
__global__ void __launch_bounds__(256) k_mkA3h(const float* __restrict__ cheb) {
    int b = blockIdx.z;
    int mtile = blockIdx.y * 64;
    int ntile = blockIdx.x * 64;
    __shared__ float tS[64][65];
    __shared__ float tC[64][65];
    __shared__ float ics[64];
    __shared__ float cmx[64];
    int tid = threadIdx.x;
    const float* Sx = g_Spre + (size_t)b * NN * NN;
    if (tid < 64) {
        ics[tid] = g_icsum[b * NN + mtile + tid] * A_SCALE;
        cmx[tid] = g_cmax[b * NN + mtile + tid];
    }
    __syncthreads();
    #pragma unroll
    for (int i = 0; i < 4; i++) {
        int idx = tid + i * 256;
        int n_loc = idx >> 4, m_loc = (idx & 15) * 4;
        size_t g = (size_t)(ntile + n_loc) * NN + mtile + m_loc;
        float4 sv = *(const float4*)&Sx[g];
        tS[m_loc + 0][n_loc] = __expf(sv.x - cmx[m_loc + 0]);
        tS[m_loc + 1][n_loc] = __expf(sv.y - cmx[m_loc + 1]);
        tS[m_loc + 2][n_loc] = __expf(sv.z - cmx[m_loc + 2]);
        tS[m_loc + 3][n_loc] = __expf(sv.w - cmx[m_loc + 3]);
    }
    __syncthreads();
    for (int kk = 0; kk < NK; kk++) {
        const float* Cb = cheb + (size_t)kk * NN * NN;
        #pragma unroll
        for (int i = 0; i < 4; i++) {
            int idx = tid + i * 256;
            int n_loc = idx >> 4, m_loc = (idx & 15) * 4;
            size_t g = (size_t)(ntile + n_loc) * NN + mtile + m_loc;
            float4 cv = *(const float4*)&Cb[g];
            tC[m_loc + 0][n_loc] = cv.x;
            tC[m_loc + 1][n_loc] = cv.y;
            tC[m_loc + 2][n_loc] = cv.z;
            tC[m_loc + 3][n_loc] = cv.w;
        }
        __syncthreads();
        int m_loc = tid >> 2, q = tid & 3;
        float icm = ics[m_loc];
        unsigned short uh[16];
        #pragma unroll
        for (int u = 0; u < 16; u++)
            uh[u] = __half_as_ushort(__float2half_rn(
                tS[m_loc][q * 16 + u] * tC[m_loc][q * 16 + u] * icm));
        uint32_t wh[8];
        #pragma unroll
        for (int p = 0; p < 8; p++)
            wh[p] = (uint32_t)uh[2 * p] | ((uint32_t)uh[2 * p + 1] << 16);
        size_t off = ((size_t)(b * 3 + kk) * NN + mtile + m_loc) * NN + ntile + q * 16;
        uint4* dh = (uint4*)(g_AT + off);
        dh[0] = make_uint4(wh[0], wh[1], wh[2], wh[3]);
        dh[1] = make_uint4(wh[4], wh[5], wh[6], wh[7]);
        __syncthreads();
    }
}

// ---------------------------------------------------------------------------
// K11b: XT[b][j][n] = fp16split( x[b][n][j] )             grid(16,12,16) x 256
// ---------------------------------------------------------------------------
__global__ void __launch_bounds__(256) k_mkXh(const float* __restrict__ x) {
    int b = blockIdx.z;
    int jtile = blockIdx.y * 64;
    int ntile = blockIdx.x * 64;
    __shared__ float tile[64][65];
    int tid = threadIdx.x;
    #pragma unroll
    for (int i = 0; i < 4; i++) {
        int idx = tid + i * 256;
        int n_loc = idx >> 4, j_loc = (idx & 15) * 4;
        size_t g = (size_t)(b * NN + ntile + n_loc) * FT + jtile + j_loc;
        float4 v = *(const float4*)&x[g];
        tile[j_loc + 0][n_loc] = v.x;
        tile[j_loc + 1][n_loc] = v.y;
        tile[j_loc + 2][n_loc] = v.z;
        tile[j_loc + 3][n_loc] = v.w;
    }
    __syncthreads();
    int j_loc = tid >> 2, q = tid & 3;
    unsigned short uh[16], ul[16];
    #pragma unroll
    for (int u = 0; u < 16; u++)
        split_h(tile[j_loc][q * 16 + u], uh[u], ul[u]);
    uint32_t wh[8], wl[8];
    #pragma unroll
    for (int p = 0; p < 8; p++) {
        wh[p] = (uint32_t)uh[2 * p] | ((uint32_t)uh[2 * p + 1] << 16);
        wl[p] = (uint32_t)ul[2 * p] | ((uint32_t)ul[2 * p + 1] << 16);
    }
    size_t off = ((size_t)b * FT + jtile + j_loc) * NN + ntile + q * 16;
    uint4* dh = (uint4*)(g_XT_hi + off);
    uint4* dl = (uint4*)(g_XT_lo + off);
    dh[0] = make_uint4(wh[0], wh[1], wh[2], wh[3]);
    dh[1] = make_uint4(wh[4], wh[5], wh[6], wh[7]);
    dl[0] = make_uint4(wl[0], wl[1], wl[2], wl[3]);
    dl[1] = make_uint4(wl[4], wl[5], wl[6], wl[7]);
}

// ---------------------------------------------------------------------------
// K12 (dominant): mma.sync fp16 GEMM, 2-term (Ah*Xh + Ah*Xl), output x2^-10.
//   Stage = KC=32 with A + Xh + Xl; CTA 128m x 128j, 8 warps, 32 stages,
//   3-stage cp.async pipeline (90KB smem, 2 CTA/SM).  grid(6, 8, 48) x 256
// ---------------------------------------------------------------------------
constexpr int STG = 10240;            // 128 rows * 80B per matrix
constexpr int STAGE_BYTES = 3 * STG;  // 30720
constexpr int MMA_SMEM = 3 * STAGE_BYTES;  // 92160

__global__ void __launch_bounds__(256, 2) k_mma2() {
    extern __shared__ __align__(16) unsigned char smb[];
    int tid = threadIdx.x, lane = tid & 31, wid = tid >> 5;
    int kb = blockIdx.z;
    int b = kb / 3, kk = kb - b * 3;
    int m0 = blockIdx.y * 128;
    int j0 = blockIdx.x * 128;
    const unsigned short* Ah = g_AT + (size_t)kb * NN * NN + (size_t)m0 * NN;
    const unsigned short* Xh = g_XT_hi + (size_t)b * FT * NN + (size_t)j0 * NN;
    const unsigned short* Xl = g_XT_lo + (size_t)b * FT * NN + (size_t)j0 * NN;
    int warp_m = wid >> 2, warp_j = wid & 3;

    float d[4][4][4];
    #pragma unroll
    for (int i = 0; i < 4; i++)
        #pragma unroll
        for (int j = 0; j < 4; j++)
            #pragma unroll
            for (int q = 0; q < 4; q++) d[i][j][q] = 0.f;

    int arow = (lane < 16) ? lane : (lane - 16);
    int ako  = (lane < 16) ? 0 : 8;
    int brow = (lane & 7) + ((lane >> 4) << 3);
    int bko  = (lane & 8) ? 8 : 0;

    auto issue = [&](int s) {
        unsigned char* buf = smb + (s % 3) * STAGE_BYTES;
        int n0 = s * 32;
        const unsigned short* srcs[3] = {Ah + n0, Xh + n0, Xl + n0};
        #pragma unroll
        for (int i = 0; i < 6; i++) {
            int mat = i >> 1;
            int idx = tid + (i & 1) * 256;
            int r = idx >> 2, c = idx & 3;
            cpasync16(smem_u32(buf + mat * STG + r * 80 + c * 16),
                      srcs[mat] + (size_t)r * NN + c * 8);
        }
        asm volatile("cp.async.commit_group;" ::: "memory");
    };

    issue(0);
    issue(1);
    for (int s = 0; s < 32; s++) {
        if (s + 2 < 32) {
            issue(s + 2);
            asm volatile("cp.async.wait_group 2;" ::: "memory");
        } else if (s + 1 < 32) {
            asm volatile("cp.async.wait_group 1;" ::: "memory");
        } else {
            asm volatile("cp.async.wait_group 0;" ::: "memory");
        }
        __syncthreads();
        unsigned char* buf = smb + (s % 3) * STAGE_BYTES;
        uint32_t aH = smem_u32(buf);
        uint32_t xH = aH + STG;
        uint32_t xL = aH + 2 * STG;
        #pragma unroll
        for (int ks = 0; ks < 2; ks++) {
            uint32_t afr[4][4], bh[2][4], bl[2][4];
            #pragma unroll
            for (int mt = 0; mt < 4; mt++)
                ldmx4(afr[mt], aH + (warp_m * 64 + mt * 16 + arow) * 80 +
                               (ks * 16 + ako) * 2);
            #pragma unroll
            for (int jp = 0; jp < 2; jp++)
                ldmx4(bh[jp], xH + (warp_j * 32 + jp * 16 + brow) * 80 +
                              (ks * 16 + bko) * 2);
            #pragma unroll
            for (int jp = 0; jp < 2; jp++)
                ldmx4(bl[jp], xL + (warp_j * 32 + jp * 16 + brow) * 80 +
                              (ks * 16 + bko) * 2);
            #pragma unroll
            for (int mt = 0; mt < 4; mt++)
                #pragma unroll
                for (int jt = 0; jt < 4; jt++)
                    mma16816h(d[mt][jt], afr[mt],
                              bh[jt >> 1][2 * (jt & 1)], bh[jt >> 1][2 * (jt & 1) + 1]);
            #pragma unroll
            for (int mt = 0; mt < 4; mt++)
                #pragma unroll
                for (int jt = 0; jt < 4; jt++)
                    mma16816h(d[mt][jt], afr[mt],
                              bl[jt >> 1][2 * (jt & 1)], bl[jt >> 1][2 * (jt & 1) + 1]);
        }
        __syncthreads();
    }

    float* ob = g_rhs_all + (size_t)(kk * NB + b) * NN * FT;
    int mb = m0 + warp_m * 64, jb = j0 + warp_j * 32;
    #pragma unroll
    for (int mt = 0; mt < 4; mt++)
        #pragma unroll
        for (int jt = 0; jt < 4; jt++) {
            int row = mb + mt * 16 + (lane >> 2);
            int col = jb + jt * 8 + 2 * (lane & 3);
            float2 v0, v1;
            v0.x = d[mt][jt][0] * A_UNSCALE;
            v0.y = d[mt][jt][1] * A_UNSCALE;
            v1.x = d[mt][jt][2] * A_UNSCALE;
            v1.y = d[mt][jt][3] * A_UNSCALE;
            *(float2*)&ob[(size_t)row * FT + col] = v0;
            *(float2*)&ob[(size_t)(row + 8) * FT + col] = v1;
        }
}

// ---------------------------------------------------------------------------
// K13: fused tail, 4 nodes/CTA, weights via LDG, 63KB smem -> 3 CTA/SM.
//   grid(256,16) x 256
// ---------------------------------------------------------------------------
constexpr int TAIL_SMEM_FLOATS = 6656 + 3072 + 6144 + 256;  // 64512B

__global__ void __launch_bounds__(256, 3) k_tail(
    const float* __restrict__ x, const float* __restrict__ Theta,
    const float* __restrict__ tcb, const float* __restrict__ rcb,
    const float* __restrict__ gma, const float* __restrict__ bet,
    float* __restrict__ out) {
    extern __shared__ float smf[];
    float* SG = smf;           // [m(4)][cc(64)][26]  6656
    float* Xs = SG + 6656;     // [m][768]            3072
    float* Z  = Xs + 3072;     // [m][1536]           6144
    float* Bc = Z + 6144;
    float* Br = Bc + 64;
    float* Ga = Br + 64;
    float* Be = Ga + 64;

    int b = blockIdx.y, m0 = blockIdx.x * 4;
    int tid = threadIdx.x;
    if (tid < 64) { Bc[tid] = tcb[tid]; Br[tid] = rcb[tid]; Ga[tid] = gma[tid]; Be[tid] = bet[tid]; }
    for (int i = tid; i < 6656; i += 256) SG[i] = 0.f;
    for (int e = tid; e < 3072; e += 256) {
        int m = e / 768, ft = e - m * 768;
        Xs[e] = x[((size_t)(b * NN + m0 + m)) * FT + ft];
    }
    __syncthreads();

    // Phase 1: sg = relu(Theta contraction). 192 units = m(4) x tg(6) x og(8)
    if (tid < 192) {
        int m = tid / 48, rr = tid - m * 48;
        int tg = rr >> 3, og = rr & 7;
        int t0 = tg * 4, o0 = og * 8;
        unsigned long long acc[4][4];
        #pragma unroll
        for (int i = 0; i < 4; i++)
            #pragma unroll
            for (int p = 0; p < 4; p++) acc[i][p] = 0ull;
        #pragma unroll
        for (int k = 0; k < NK; k++) {
            const float* gr = g_rhs_all +
                ((size_t)(k * NB + b) * NN + m0 + m) * FT;
            const float* th = Theta + k * 2048 + o0;
            #pragma unroll 4
            for (int f = 0; f < NF; f++) {
                float4 bk = *(const float4*)&gr[f * 24 + t0];
                const unsigned long long* tp =
                    (const unsigned long long*)(th + f * 64);
                unsigned long long bp0 = pack2(bk.x), bp1 = pack2(bk.y);
                unsigned long long bp2 = pack2(bk.z), bp3 = pack2(bk.w);
                #pragma unroll
                for (int p = 0; p < 4; p++) {
                    unsigned long long tv = tp[p];
                    ffma2(acc[0][p], bp0, tv);
                    ffma2(acc[1][p], bp1, tv);
                    ffma2(acc[2][p], bp2, tv);
                    ffma2(acc[3][p], bp3, tv);
                }
            }
        }
        #pragma unroll
        for (int p = 0; p < 4; p++) {
            int o = o0 + 2 * p;
            #pragma unroll
            for (int i = 0; i < 4; i++) {
                SG[(m * 64 + o) * 26 + t0 + i + 1] = fmaxf(lo32(acc[i][p]), 0.f);
                SG[(m * 64 + o + 1) * 26 + t0 + i + 1] = fmaxf(hi32(acc[i][p]), 0.f);
            }
        }
    }
    __syncthreads();

    // Phase 2: z = relu(timeconv + residual). 512 units
    #pragma unroll
    for (int rep = 0; rep < 2; rep++) {
        int u = tid + rep * 256;
        int m = u >> 7, rr = u & 127;
        int tg = rr >> 4, cg = rr & 15;
        int t0 = tg * 3, c0 = cg * 4;
        unsigned long long z[3][2];
        #pragma unroll
        for (int i = 0; i < 3; i++) { z[i][0] = 0ull; z[i][1] = 0ull; }
        const float* sgm = &SG[m * 1664];
        for (int cc = 0; cc < NCC; cc++) {
            const float* srow = &sgm[cc * 26 + t0];
            unsigned long long sp[5];
            #pragma unroll
            for (int j = 0; j < 5; j++) sp[j] = pack2(srow[j]);
            const float* wbase = &g_Wt[cc * 192 + c0];
            #pragma unroll
            for (int r = 0; r < 3; r++) {
                const unsigned long long* wp =
                    (const unsigned long long*)(wbase + r * 64);
                unsigned long long w0 = wp[0], w1 = wp[1];
                #pragma unroll
                for (int i = 0; i < 3; i++) {
                    ffma2(z[i][0], sp[i + r], w0);
                    ffma2(z[i][1], sp[i + r], w1);
                }
            }
        }
        const float* xm = &Xs[m * 768];
        #pragma unroll 4
        for (int f = 0; f < NF; f++) {
            const float* xr = &xm[f * 24 + t0];
            unsigned long long xp0 = pack2(xr[0]);
            unsigned long long xp1 = pack2(xr[1]);
            unsigned long long xp2 = pack2(xr[2]);
            const unsigned long long* wp =
                (const unsigned long long*)(&g_Wr[f * 64 + c0]);
            unsigned long long w0 = wp[0], w1 = wp[1];
            ffma2(z[0][0], xp0, w0); ffma2(z[0][1], xp0, w1);
            ffma2(z[1][0], xp1, w0); ffma2(z[1][1], xp1, w1);
            ffma2(z[2][0], xp2, w0); ffma2(z[2][1], xp2, w1);
        }
        float* zb = &Z[m * 1536];
        #pragma unroll
        for (int p = 0; p < 2; p++) {
            int c = c0 + 2 * p;
            float b0 = Bc[c] + Br[c], b1 = Bc[c + 1] + Br[c + 1];
            #pragma unroll
            for (int i = 0; i < 3; i++) {
                zb[c * 24 + t0 + i] = fmaxf(lo32(z[i][p]) + b0, 0.f);
                zb[(c + 1) * 24 + t0 + i] = fmaxf(hi32(z[i][p]) + b1, 0.f);
            }
        }
    }
    __syncthreads();

    // Phase 3: LayerNorm over ct, write out[b,m,ct,t]
    if (tid < 96) {
        int m = tid / 24, t = tid - m * 24;
        const float* zz = &Z[m * 1536 + t];
        float mu = 0.f;
        #pragma unroll
        for (int c = 0; c < NCT; c++) mu += zz[c * NT];
        mu *= (1.f / 64.f);
        float var = 0.f;
        #pragma unroll
        for (int c = 0; c < NCT; c++) { float dd = zz[c * NT] - mu; var += dd * dd; }
        var *= (1.f / 64.f);
        float rs = rsqrtf(var + 1e-5f);
        float* op = out + ((size_t)(b * NN + m0 + m) * NCT) * NT + t;
        #pragma unroll
        for (int c = 0; c < NCT; c++)
            op[c * NT] = (zz[c * NT] - mu) * rs * Ga[c] + Be[c];
    }
}

// ---------------------------------------------------------------------------
extern "C" void kernel_launch(void* const* d_in, const int* in_sizes, int n_in,
                              void* d_out, int out_size) {
    const float* x     = (const float*)d_in[0];
    const float* W1    = (const float*)d_in[1];
    const float* W2    = (const float*)d_in[2];
    const float* W3    = (const float*)d_in[3];
    const float* U1    = (const float*)d_in[4];
    const float* U2    = (const float*)d_in[5];
    const float* U3    = (const float*)d_in[6];
    const float* cheb  = (const float*)d_in[7];
    const float* Theta = (const float*)d_in[8];
    const float* tc_w  = (const float*)d_in[9];
    const float* tc_b  = (const float*)d_in[10];
    const float* rc_w  = (const float*)d_in[11];
    const float* rc_b  = (const float*)d_in[12];
    const float* gamma = (const float*)d_in[13];
    const float* beta  = (const float*)d_in[14];
    float* out = (float*)d_out;

    constexpr int RX_SMEM = 32 * 769 * 4;  // 98432
    cudaFuncSetAttribute(k_rx, cudaFuncAttributeMaxDynamicSharedMemorySize,
                         RX_SMEM);
    cudaFuncSetAttribute(k_tail, cudaFuncAttributeMaxDynamicSharedMemorySize,
                         TAIL_SMEM_FLOATS * 4);
    cudaFuncSetAttribute(k_mma2, cudaFuncAttributeMaxDynamicSharedMemorySize,
                         MMA_SMEM);

    k_prep_w<<<1, 256>>>(tc_w, rc_w);
    // fused x-reader: lhs partials + rhs_t + xw3
    k_rx<<<dim3(32, NB), 256, RX_SMEM>>>(x, U1, U3, W3);
    k_lhs_red<<<NB, 256>>>();
    // temporal attention
    k_epre<<<dim3(NT, NB), 256>>>(U2);
    k_esm<<<dim3(NT, NB), 32>>>();
    k_ew1<<<NB, 32>>>(W1);
    // spatial attention
    k_lhs2<<<NB * 128, 256>>>(x, W2);
    k_rhs_s2<<<dim3(NN / 32, NB), 256>>>();
    k_spre<<<dim3(16, 16, NB), 256>>>();
    k_cms<<<dim3(NN / 32, NB), 256>>>();
    // operand prep (fp16, exp fused in)
    k_mkA3h<<<dim3(16, 16, NB), 256>>>(cheb);
    k_mkXh<<<dim3(16, 12, NB), 256>>>(x);
    // chebyshev graph conv on mma.sync (2-term fp16)
    k_mma2<<<dim3(6, 8, NB * NK), 256, MMA_SMEM>>>();
    // fused Theta + timeconv + residual + LN
    k_tail<<<dim3(NN / 4, NB), 256, TAIL_SMEM_FLOATS * 4>>>(
        x, Theta, tc_b, rc_b, gamma, beta, out);
}